// round 3
// baseline (speedup 1.0000x reference)
#include <cuda_runtime.h>
#include <math.h>

#define NA 50000
#define NP 50000
#define EE 600000
#define HH 8
#define DD 16
#define CC 128
#define OUTC 16
#define FA 256
#define FP 128
#define EPSV 1e-5f

// ---------------- device scratch (static, no allocation) ----------------
__device__ float    g_h_a[(size_t)NA * CC];
__device__ float    g_h_p[(size_t)NP * CC];
__device__ float    g_as_ap[NA * HH];
__device__ float    g_ad_ap[NP * HH];
__device__ float    g_as_pp[NP * HH];
__device__ float    g_ad_pp[NP * HH];
__device__ int      g_cnt[2 * NP];
__device__ int      g_cur[2 * NP];
__device__ int      g_rowptr[2 * (NP + 1)];
__device__ int      g_srcs[2 * (size_t)EE];       // src ids sorted by dst
__device__ float    g_out01[2 * (size_t)NP * CC]; // [r][n][c], relu-applied
__device__ float    g_wsum[2];
__device__ float    g_beta[2];
__device__ float    g_S1[CC];
__device__ float    g_S2[CC];
__device__ float    g_nA[CC];
__device__ float    g_nB[CC];

// ---------------- init ----------------
__global__ void init_kernel() {
    int idx = blockIdx.x * blockDim.x + threadIdx.x;
    int stride = gridDim.x * blockDim.x;
    for (int i = idx; i < 2 * NP; i += stride) g_cnt[i] = 0;
    if (idx < CC) { g_S1[idx] = 0.f; g_S2[idx] = 0.f; }
    if (idx < 2)  g_wsum[idx] = 0.f;
}

// ---------------- CSR build: histogram ----------------
__global__ void hist_kernel(const int* __restrict__ e_ap, const int* __restrict__ e_pp) {
    int idx = blockIdx.x * blockDim.x + threadIdx.x;
    if (idx >= 2 * EE) return;
    int t = (idx >= EE);
    int e = idx - t * EE;
    const int* ed = t ? e_pp : e_ap;
    int dst = ed[EE + e];
    atomicAdd(&g_cnt[t * NP + dst], 1);
}

// ---------------- CSR build: single-block scan per type ----------------
#define SCAN_T 1024
#define SCAN_CHUNK 49
__global__ void scan_kernel() {
    int t = blockIdx.x;
    int tid = threadIdx.x;
    const int* cnt = g_cnt + t * NP;
    int* rowptr = g_rowptr + t * (NP + 1);
    int* cur = g_cur + t * NP;

    int lo = tid * SCAN_CHUNK;
    int hi = lo + SCAN_CHUNK; if (hi > NP) hi = NP;
    int tsum = 0;
    for (int i = lo; i < hi; i++) tsum += cnt[i];

    __shared__ int sh[SCAN_T];
    sh[tid] = tsum;
    __syncthreads();
    for (int off = 1; off < SCAN_T; off <<= 1) {
        int v = (tid >= off) ? sh[tid - off] : 0;
        __syncthreads();
        sh[tid] += v;
        __syncthreads();
    }
    int running = sh[tid] - tsum;
    for (int i = lo; i < hi; i++) {
        rowptr[i] = running;
        cur[i] = running;
        running += cnt[i];
    }
    if (tid == 0) rowptr[NP] = EE;
}

// ---------------- CSR build: scatter ----------------
__global__ void scatter_kernel(const int* __restrict__ e_ap, const int* __restrict__ e_pp) {
    int idx = blockIdx.x * blockDim.x + threadIdx.x;
    if (idx >= 2 * EE) return;
    int t = (idx >= EE);
    int e = idx - t * EE;
    const int* ed = t ? e_pp : e_ap;
    int src = ed[e];
    int dst = ed[EE + e];
    int pos = atomicAdd(&g_cur[t * NP + dst], 1);
    g_srcs[(size_t)t * EE + pos] = src;
}

// ---------------- tiled fp32 GEMM: [N, KDIM] x [KDIM, 128] + bias ----------------
// BM=128, BN=128, BK=16, 256 threads, 8x8 thread tile
template <int KDIM>
__global__ __launch_bounds__(256) void gemm_proj_kernel(const float* __restrict__ X,
                                 const float* __restrict__ W,
                                 const float* __restrict__ bias,
                                 float* __restrict__ out, int Nrows) {
    __shared__ float As[16][132];
    __shared__ float Bs[16][128];
    int tid = threadIdx.x;
    int tx = tid & 15, ty = tid >> 4;
    int row0 = blockIdx.x * 128;

    float acc[8][8];
#pragma unroll
    for (int m = 0; m < 8; m++)
#pragma unroll
        for (int n = 0; n < 8; n++) acc[m][n] = 0.f;

    int ar = tid >> 1;            // 0..127
    int ak0 = (tid & 1) * 8;      // 0 or 8
    int bk = tid >> 4;            // 0..15
    int bc0 = (tid & 15) * 8;

    for (int k0 = 0; k0 < KDIM; k0 += 16) {
        int grow = row0 + ar;
        float4 av0 = make_float4(0.f, 0.f, 0.f, 0.f);
        float4 av1 = av0;
        if (grow < Nrows) {
            const float* xp = X + (size_t)grow * KDIM + k0 + ak0;
            av0 = *(const float4*)(xp);
            av1 = *(const float4*)(xp + 4);
        }
        As[ak0 + 0][ar] = av0.x; As[ak0 + 1][ar] = av0.y;
        As[ak0 + 2][ar] = av0.z; As[ak0 + 3][ar] = av0.w;
        As[ak0 + 4][ar] = av1.x; As[ak0 + 5][ar] = av1.y;
        As[ak0 + 6][ar] = av1.z; As[ak0 + 7][ar] = av1.w;

        const float* wp = W + (size_t)(k0 + bk) * CC + bc0;
        float4 bv0 = *(const float4*)(wp);
        float4 bv1 = *(const float4*)(wp + 4);
        *(float4*)&Bs[bk][bc0] = bv0;
        *(float4*)&Bs[bk][bc0 + 4] = bv1;
        __syncthreads();

#pragma unroll
        for (int kk = 0; kk < 16; kk++) {
            float b[8], a[8];
            float4 b0 = *(const float4*)&Bs[kk][tx * 8];
            float4 b1 = *(const float4*)&Bs[kk][tx * 8 + 4];
            b[0] = b0.x; b[1] = b0.y; b[2] = b0.z; b[3] = b0.w;
            b[4] = b1.x; b[5] = b1.y; b[6] = b1.z; b[7] = b1.w;
            float4 a0 = *(const float4*)&As[kk][ty * 8];
            float4 a1 = *(const float4*)&As[kk][ty * 8 + 4];
            a[0] = a0.x; a[1] = a0.y; a[2] = a0.z; a[3] = a0.w;
            a[4] = a1.x; a[5] = a1.y; a[6] = a1.z; a[7] = a1.w;
#pragma unroll
            for (int m = 0; m < 8; m++)
#pragma unroll
                for (int n = 0; n < 8; n++)
                    acc[m][n] += a[m] * b[n];
        }
        __syncthreads();
    }

    float4 bb0 = *(const float4*)(bias + tx * 8);
    float4 bb1 = *(const float4*)(bias + tx * 8 + 4);
#pragma unroll
    for (int m = 0; m < 8; m++) {
        int grow = row0 + ty * 8 + m;
        if (grow < Nrows) {
            float* op = out + (size_t)grow * CC + tx * 8;
            float4 v0 = make_float4(acc[m][0] + bb0.x, acc[m][1] + bb0.y,
                                    acc[m][2] + bb0.z, acc[m][3] + bb0.w);
            float4 v1 = make_float4(acc[m][4] + bb1.x, acc[m][5] + bb1.y,
                                    acc[m][6] + bb1.z, acc[m][7] + bb1.w);
            *(float4*)(op) = v0;
            *(float4*)(op + 4) = v1;
        }
    }
}

// ---------------- per-node-head attention logits ----------------
__global__ void alpha1_kernel(const float* __restrict__ Hm, const float* __restrict__ att,
                              float* __restrict__ out, int N) {
    __shared__ float a[CC];
    if (threadIdx.x < CC) a[threadIdx.x] = att[threadIdx.x];
    __syncthreads();
    int idx = blockIdx.x * blockDim.x + threadIdx.x;
    if (idx >= N * HH) return;
    int h = idx & 7, n = idx >> 3;
    const float4* hp = (const float4*)(Hm + (size_t)n * CC + h * DD);
    const float4* ap = (const float4*)(a + h * DD);
    float s = 0.f;
#pragma unroll
    for (int j = 0; j < 4; j++) {
        float4 x = hp[j], w = ap[j];
        s += x.x * w.x + x.y * w.y + x.z * w.z + x.w * w.w;
    }
    out[idx] = s;
}

__global__ void alpha3_kernel(const float* __restrict__ Hm,
                              const float* __restrict__ a1, const float* __restrict__ a2,
                              const float* __restrict__ a3,
                              float* __restrict__ o1, float* __restrict__ o2,
                              float* __restrict__ o3, int N) {
    __shared__ float s1[CC], s2[CC], s3[CC];
    if (threadIdx.x < CC) {
        s1[threadIdx.x] = a1[threadIdx.x];
        s2[threadIdx.x] = a2[threadIdx.x];
        s3[threadIdx.x] = a3[threadIdx.x];
    }
    __syncthreads();
    int idx = blockIdx.x * blockDim.x + threadIdx.x;
    if (idx >= N * HH) return;
    int h = idx & 7, n = idx >> 3;
    const float4* hp = (const float4*)(Hm + (size_t)n * CC + h * DD);
    const float4* p1 = (const float4*)(s1 + h * DD);
    const float4* p2 = (const float4*)(s2 + h * DD);
    const float4* p3 = (const float4*)(s3 + h * DD);
    float r1 = 0.f, r2 = 0.f, r3 = 0.f;
#pragma unroll
    for (int j = 0; j < 4; j++) {
        float4 x = hp[j];
        float4 w1 = p1[j], w2 = p2[j], w3 = p3[j];
        r1 += x.x * w1.x + x.y * w1.y + x.z * w1.z + x.w * w1.w;
        r2 += x.x * w2.x + x.y * w2.y + x.z * w2.z + x.w * w2.w;
        r3 += x.x * w3.x + x.y * w3.y + x.z * w3.z + x.w * w3.w;
    }
    o1[idx] = r1; o2[idx] = r2; o3[idx] = r3;
}

// ---------------- single-pass fused edge softmax + aggregation (warp per dst) ----------------
// softmax without max-shift (logits bounded; shift-invariant identity) and
// post-aggregation normalization: out = relu( (sum_i e_i h_i) / sum_i e_i )
__global__ void edge_fused_kernel(const int* __restrict__ rowptr,
                                  const int* __restrict__ srcs,
                                  const float* __restrict__ as,
                                  const float* __restrict__ ad,
                                  const float* __restrict__ Hsrc,
                                  float* __restrict__ outp) {
    int warp = threadIdx.x >> 5;
    int lane = threadIdx.x & 31;
    int dst = blockIdx.x * 8 + warp;
    if (dst >= NP) return;

    int base = rowptr[dst];
    int deg = rowptr[dst + 1] - base;

    float* ow = outp + (size_t)dst * CC;
    if (deg == 0) {
        *(float4*)(ow + lane * 4) = make_float4(0.f, 0.f, 0.f, 0.f);
        return;
    }

    int myh = lane >> 2;
    float advh = ad[dst * HH + myh];

    float4 acc = make_float4(0.f, 0.f, 0.f, 0.f);
    float denom = 0.f;
    for (int i = 0; i < deg; i++) {
        int s = srcs[base + i];                       // broadcast
        float v = as[s * HH + myh] + advh;
        v = (v >= 0.f) ? v : 0.2f * v;
        float e = __expf(v);
        denom += e;
        float4 hv = *(const float4*)(Hsrc + (size_t)s * CC + lane * 4);
        acc.x += e * hv.x; acc.y += e * hv.y;
        acc.z += e * hv.z; acc.w += e * hv.w;
    }
    float inv = 1.f / denom;
    float4 v = make_float4(fmaxf(acc.x * inv, 0.f), fmaxf(acc.y * inv, 0.f),
                           fmaxf(acc.z * inv, 0.f), fmaxf(acc.w * inv, 0.f));
    *(float4*)(ow + lane * 4) = v;
}

// ---------------- semantic attention (out01 already relu'd) ----------------
__global__ __launch_bounds__(256) void semantic_kernel(const float* __restrict__ kW,
                                const float* __restrict__ kb,
                                const float* __restrict__ q) {
    const float* A = g_out01 + (size_t)blockIdx.y * NP * CC;
    __shared__ float As[16][132];
    __shared__ float Bs[16][128];
    __shared__ float red[256];
    int tid = threadIdx.x;
    int tx = tid & 15, ty = tid >> 4;
    int row0 = blockIdx.x * 128;

    float acc[8][8];
#pragma unroll
    for (int m = 0; m < 8; m++)
#pragma unroll
        for (int n = 0; n < 8; n++) acc[m][n] = 0.f;

    int ar = tid >> 1, ak0 = (tid & 1) * 8;
    int bk = tid >> 4, bc0 = (tid & 15) * 8;

    for (int k0 = 0; k0 < CC; k0 += 16) {
        int grow = row0 + ar;
        float4 av0 = make_float4(0.f, 0.f, 0.f, 0.f);
        float4 av1 = av0;
        if (grow < NP) {
            const float* xp = A + (size_t)grow * CC + k0 + ak0;
            av0 = *(const float4*)(xp);
            av1 = *(const float4*)(xp + 4);
        }
        As[ak0 + 0][ar] = av0.x; As[ak0 + 1][ar] = av0.y;
        As[ak0 + 2][ar] = av0.z; As[ak0 + 3][ar] = av0.w;
        As[ak0 + 4][ar] = av1.x; As[ak0 + 5][ar] = av1.y;
        As[ak0 + 6][ar] = av1.z; As[ak0 + 7][ar] = av1.w;

        const float* wp = kW + (size_t)(k0 + bk) * CC + bc0;
        float4 bv0 = *(const float4*)(wp);
        float4 bv1 = *(const float4*)(wp + 4);
        *(float4*)&Bs[bk][bc0] = bv0;
        *(float4*)&Bs[bk][bc0 + 4] = bv1;
        __syncthreads();

#pragma unroll
        for (int kk = 0; kk < 16; kk++) {
            float b[8], a[8];
            float4 b0 = *(const float4*)&Bs[kk][tx * 8];
            float4 b1 = *(const float4*)&Bs[kk][tx * 8 + 4];
            b[0] = b0.x; b[1] = b0.y; b[2] = b0.z; b[3] = b0.w;
            b[4] = b1.x; b[5] = b1.y; b[6] = b1.z; b[7] = b1.w;
            float4 a0 = *(const float4*)&As[kk][ty * 8];
            float4 a1 = *(const float4*)&As[kk][ty * 8 + 4];
            a[0] = a0.x; a[1] = a0.y; a[2] = a0.z; a[3] = a0.w;
            a[4] = a1.x; a[5] = a1.y; a[6] = a1.z; a[7] = a1.w;
#pragma unroll
            for (int m = 0; m < 8; m++)
#pragma unroll
                for (int n = 0; n < 8; n++)
                    acc[m][n] += a[m] * b[n];
        }
        __syncthreads();
    }

    float kbv[8], qv[8];
    {
        float4 k0v = *(const float4*)(kb + tx * 8);
        float4 k1v = *(const float4*)(kb + tx * 8 + 4);
        kbv[0] = k0v.x; kbv[1] = k0v.y; kbv[2] = k0v.z; kbv[3] = k0v.w;
        kbv[4] = k1v.x; kbv[5] = k1v.y; kbv[6] = k1v.z; kbv[7] = k1v.w;
        float4 q0v = *(const float4*)(q + tx * 8);
        float4 q1v = *(const float4*)(q + tx * 8 + 4);
        qv[0] = q0v.x; qv[1] = q0v.y; qv[2] = q0v.z; qv[3] = q0v.w;
        qv[4] = q1v.x; qv[5] = q1v.y; qv[6] = q1v.z; qv[7] = q1v.w;
    }
    float part = 0.f;
#pragma unroll
    for (int m = 0; m < 8; m++) {
        int grow = row0 + ty * 8 + m;
        if (grow < NP) {
#pragma unroll
            for (int n = 0; n < 8; n++)
                part += tanhf(acc[m][n] + kbv[n]) * qv[n];
        }
    }
    red[tid] = part;
    __syncthreads();
    for (int s = 128; s > 0; s >>= 1) {
        if (tid < s) red[tid] += red[tid + s];
        __syncthreads();
    }
    if (tid == 0) atomicAdd(&g_wsum[blockIdx.y], red[0]);
}

__global__ void beta_kernel() {
    float w0 = g_wsum[0] / (float)NP;
    float w1 = g_wsum[1] / (float)NP;
    float m = fmaxf(w0, w1);
    float e0 = expf(w0 - m), e1 = expf(w1 - m);
    float s = e0 + e1;
    g_beta[0] = e0 / s;
    g_beta[1] = e1 / s;
}

// ---------------- per-channel stats of combined output ----------------
#define STAT_ROWS 512
__global__ void stats_kernel() {
    int c = threadIdx.x;
    float b0 = g_beta[0], b1 = g_beta[1];
    const float* o0 = g_out01;
    const float* o1 = g_out01 + (size_t)NP * CC;
    int r0 = blockIdx.x * STAT_ROWS;
    int r1 = r0 + STAT_ROWS; if (r1 > NP) r1 = NP;
    float s1 = 0.f, s2 = 0.f;
    for (int r = r0; r < r1; r++) {
        float v = b0 * o0[(size_t)r * CC + c] + b1 * o1[(size_t)r * CC + c];
        s1 += v;
        s2 += v * v;
    }
    atomicAdd(&g_S1[c], s1);
    atomicAdd(&g_S2[c], s2);
}

__global__ void normparam_kernel(const float* __restrict__ norm_w,
                                 const float* __restrict__ norm_b,
                                 const float* __restrict__ norm_ms) {
    int c = threadIdx.x;
    float mean = g_S1[c] / (float)NP;
    float eo2 = g_S2[c] / (float)NP;
    float mm = mean * norm_ms[c];
    float var = eo2 - 2.f * mm * mean + mm * mm;
    float A = norm_w[c] * rsqrtf(var + EPSV);
    g_nA[c] = A;
    g_nB[c] = norm_b[c] - mm * A;
}

// ---------------- fused normalize + classifier ----------------
__global__ void final_kernel(const float* __restrict__ linW,
                             const float* __restrict__ linb,
                             float* __restrict__ y) {
    __shared__ float rowbuf[16][CC];
    __shared__ float lw[CC * OUTC];
    __shared__ float lb[OUTC];
    int tid = threadIdx.x;
    for (int i = tid; i < CC * OUTC; i += 256) lw[i] = linW[i];
    if (tid < OUTC) lb[tid] = linb[tid];
    float b0 = g_beta[0], b1 = g_beta[1];
    const float* o0 = g_out01;
    const float* o1 = g_out01 + (size_t)NP * CC;
    int nrow0 = blockIdx.x * 16;
#pragma unroll
    for (int j = 0; j < 8; j++) {
        int i = tid + j * 256;
        int r = i >> 7, c = i & 127;
        int gr = nrow0 + r;
        float v = 0.f;
        if (gr < NP) {
            v = b0 * o0[(size_t)gr * CC + c] + b1 * o1[(size_t)gr * CC + c];
            v = v * g_nA[c] + g_nB[c];
        }
        rowbuf[r][c] = v;
    }
    __syncthreads();
    int r = tid >> 4, o = tid & 15;
    int gr = nrow0 + r;
    if (gr < NP) {
        float s = lb[o];
#pragma unroll
        for (int c = 0; c < CC; c++) s += rowbuf[r][c] * lw[c * OUTC + o];
        y[(size_t)gr * OUTC + o] = s;
    }
}

// ---------------- launch ----------------
extern "C" void kernel_launch(void* const* d_in, const int* in_sizes, int n_in,
                              void* d_out, int out_size) {
    const float* x_author = (const float*)d_in[0];
    const float* x_paper  = (const float*)d_in[1];
    const float* W_a      = (const float*)d_in[2];
    const float* b_a      = (const float*)d_in[3];
    const float* W_p      = (const float*)d_in[4];
    const float* b_p      = (const float*)d_in[5];
    const float* att_src_ap = (const float*)d_in[6];
    const float* att_dst_ap = (const float*)d_in[7];
    const float* att_src_pp = (const float*)d_in[8];
    const float* att_dst_pp = (const float*)d_in[9];
    const float* k_W      = (const float*)d_in[10];
    const float* k_b      = (const float*)d_in[11];
    const float* q        = (const float*)d_in[12];
    const float* norm_w   = (const float*)d_in[13];
    const float* norm_b   = (const float*)d_in[14];
    const float* norm_ms  = (const float*)d_in[15];
    const float* lin_W    = (const float*)d_in[16];
    const float* lin_b    = (const float*)d_in[17];
    const int*   edge_ap  = (const int*)d_in[18];
    const int*   edge_pp  = (const int*)d_in[19];
    float* y = (float*)d_out;

    float *p_h_a, *p_h_p, *p_as_ap, *p_ad_ap, *p_as_pp, *p_ad_pp, *p_out;
    int *p_rowptr, *p_srcs;
    cudaGetSymbolAddress((void**)&p_h_a, g_h_a);
    cudaGetSymbolAddress((void**)&p_h_p, g_h_p);
    cudaGetSymbolAddress((void**)&p_as_ap, g_as_ap);
    cudaGetSymbolAddress((void**)&p_ad_ap, g_ad_ap);
    cudaGetSymbolAddress((void**)&p_as_pp, g_as_pp);
    cudaGetSymbolAddress((void**)&p_ad_pp, g_ad_pp);
    cudaGetSymbolAddress((void**)&p_rowptr, g_rowptr);
    cudaGetSymbolAddress((void**)&p_srcs, g_srcs);
    cudaGetSymbolAddress((void**)&p_out, g_out01);

    // 0. init
    init_kernel<<<128, 256>>>();

    // 1. CSR build (both edge types)
    hist_kernel<<<(2 * EE + 255) / 256, 256>>>(edge_ap, edge_pp);
    scan_kernel<<<2, SCAN_T>>>();
    scatter_kernel<<<(2 * EE + 255) / 256, 256>>>(edge_ap, edge_pp);

    // 2. projections
    gemm_proj_kernel<FA><<<(NA + 127) / 128, 256>>>(x_author, W_a, b_a, p_h_a, NA);
    gemm_proj_kernel<FP><<<(NP + 127) / 128, 256>>>(x_paper, W_p, b_p, p_h_p, NP);

    // 3. attention logits per node
    alpha1_kernel<<<(NA * HH + 255) / 256, 256>>>(p_h_a, att_src_ap, p_as_ap, NA);
    alpha3_kernel<<<(NP * HH + 255) / 256, 256>>>(p_h_p, att_dst_ap, att_src_pp, att_dst_pp,
                                                  p_ad_ap, p_as_pp, p_ad_pp, NP);

    // 4. single-pass fused edge softmax + aggregation (no atomics, no scratch)
    edge_fused_kernel<<<(NP + 7) / 8, 256>>>(p_rowptr, p_srcs,
                                             p_as_ap, p_ad_ap, p_h_a, p_out);
    edge_fused_kernel<<<(NP + 7) / 8, 256>>>(p_rowptr + (NP + 1), p_srcs + EE,
                                             p_as_pp, p_ad_pp, p_h_p,
                                             p_out + (size_t)NP * CC);

    // 5. semantic attention
    dim3 sgrid((NP + 127) / 128, 2);
    semantic_kernel<<<sgrid, 256>>>(k_W, k_b, q);
    beta_kernel<<<1, 1>>>();

    // 6. GraphNorm stats + params
    stats_kernel<<<(NP + STAT_ROWS - 1) / STAT_ROWS, CC>>>();
    normparam_kernel<<<1, CC>>>(norm_w, norm_b, norm_ms);

    // 7. normalize + classify
    final_kernel<<<(NP + 15) / 16, 256>>>(lin_W, lin_b, y);
}

// round 4
// speedup vs baseline: 1.0983x; 1.0983x over previous
#include <cuda_runtime.h>
#include <math.h>
#include <stdint.h>

#define NA 50000
#define NP 50000
#define EE 600000
#define HH 8
#define DD 16
#define CC 128
#define OUTC 16
#define FA 256
#define FP 128
#define EPSV 1e-5f

// ---------------- device scratch (static, no allocation) ----------------
__device__ float    g_h_a[(size_t)NA * CC];
__device__ float    g_h_p[(size_t)NP * CC];
__device__ float    g_as_ap[NA * HH];
__device__ float    g_ad_ap[NP * HH];
__device__ float    g_as_pp[NP * HH];
__device__ float    g_ad_pp[NP * HH];
__device__ int      g_cnt[2 * NP];
__device__ int      g_cur[2 * NP];
__device__ int      g_rowptr[2 * (NP + 1)];
__device__ int      g_srcs[2 * (size_t)EE];
__device__ float    g_out01[2 * (size_t)NP * CC]; // relu-applied
__device__ float    g_wsum[2];
__device__ float    g_beta[2];
__device__ float    g_S1[CC];
__device__ float    g_S2[CC];
__device__ float    g_nA[CC];
__device__ float    g_nB[CC];

// ---------------- helpers ----------------
__device__ __forceinline__ float tanh_fast(float x) {
    float y;
    asm("tanh.approx.f32 %0, %1;" : "=f"(y) : "f"(x));
    return y;
}
__device__ __forceinline__ void cp16(uint32_t dst, const void* src, int sz) {
    asm volatile("cp.async.ca.shared.global [%0], [%1], 16, %2;"
                 :: "r"(dst), "l"(src), "r"(sz));
}
__device__ __forceinline__ void cp_commit() {
    asm volatile("cp.async.commit_group;");
}
__device__ __forceinline__ void cp_wait1() {
    asm volatile("cp.async.wait_group 1;");
}
__device__ __forceinline__ void cp_wait0() {
    asm volatile("cp.async.wait_group 0;");
}

// ---------------- init ----------------
__global__ void init_kernel() {
    int idx = blockIdx.x * blockDim.x + threadIdx.x;
    int stride = gridDim.x * blockDim.x;
    for (int i = idx; i < 2 * NP; i += stride) g_cnt[i] = 0;
    if (idx < CC) { g_S1[idx] = 0.f; g_S2[idx] = 0.f; }
    if (idx < 2)  g_wsum[idx] = 0.f;
}

// ---------------- CSR build ----------------
__global__ void hist_kernel(const int* __restrict__ e_ap, const int* __restrict__ e_pp) {
    int idx = blockIdx.x * blockDim.x + threadIdx.x;
    if (idx >= 2 * EE) return;
    int t = (idx >= EE);
    int e = idx - t * EE;
    const int* ed = t ? e_pp : e_ap;
    int dst = ed[EE + e];
    atomicAdd(&g_cnt[t * NP + dst], 1);
}

#define SCAN_T 1024
#define SCAN_CHUNK 49
__global__ void scan_kernel() {
    int t = blockIdx.x;
    int tid = threadIdx.x;
    const int* cnt = g_cnt + t * NP;
    int* rowptr = g_rowptr + t * (NP + 1);
    int* cur = g_cur + t * NP;

    int lo = tid * SCAN_CHUNK;
    int hi = lo + SCAN_CHUNK; if (hi > NP) hi = NP;
    int tsum = 0;
    for (int i = lo; i < hi; i++) tsum += cnt[i];

    __shared__ int sh[SCAN_T];
    sh[tid] = tsum;
    __syncthreads();
    for (int off = 1; off < SCAN_T; off <<= 1) {
        int v = (tid >= off) ? sh[tid - off] : 0;
        __syncthreads();
        sh[tid] += v;
        __syncthreads();
    }
    int running = sh[tid] - tsum;
    for (int i = lo; i < hi; i++) {
        rowptr[i] = running;
        cur[i] = running;
        running += cnt[i];
    }
    if (tid == 0) rowptr[NP] = EE;
}

__global__ void scatter_kernel(const int* __restrict__ e_ap, const int* __restrict__ e_pp) {
    int idx = blockIdx.x * blockDim.x + threadIdx.x;
    if (idx >= 2 * EE) return;
    int t = (idx >= EE);
    int e = idx - t * EE;
    const int* ed = t ? e_pp : e_ap;
    int src = ed[e];
    int dst = ed[EE + e];
    int pos = atomicAdd(&g_cur[t * NP + dst], 1);
    g_srcs[(size_t)t * EE + pos] = src;
}

// ---------------- double-buffered fp32 GEMM: [N,KDIM] x [KDIM,128] + bias ----------------
// BM=64, BN=128, BK=16, 256 threads, 8x4 thread tile, cp.async 2-stage pipeline
template <int KDIM>
__global__ __launch_bounds__(256) void gemm_proj_kernel(
        const float* __restrict__ X, const float* __restrict__ W,
        const float* __restrict__ bias, float* __restrict__ out, int Nrows) {
    __shared__ float As[2][64 * 16];
    __shared__ float Bs[2][16 * 128];
    int tid = threadIdx.x;
    int tx = tid & 31, ty = tid >> 5;
    int row0 = blockIdx.x * 64;

    // loader indices
    int lar = tid >> 2;           // A row 0..63
    int lak = (tid & 3) * 4;      // A k 0,4,8,12
    int lbk = tid >> 4;           // B k 0..15
    int lbc = (tid & 15) * 8;     // B col

    int garow = row0 + lar;
    int aok = (garow < Nrows) ? 16 : 0;
    const float* abase = X + (size_t)(aok ? garow : 0) * KDIM + lak;

    uint32_t sA0 = (uint32_t)__cvta_generic_to_shared(&As[0][lar * 16 + lak]);
    uint32_t sA1 = (uint32_t)__cvta_generic_to_shared(&As[1][lar * 16 + lak]);
    uint32_t sB0 = (uint32_t)__cvta_generic_to_shared(&Bs[0][lbk * 128 + lbc]);
    uint32_t sB1 = (uint32_t)__cvta_generic_to_shared(&Bs[1][lbk * 128 + lbc]);
    const float* bbase = W + (size_t)lbk * CC + lbc;

    const int NT = KDIM / 16;

    // preload tile 0
    cp16(sA0, abase, aok);
    cp16(sB0, bbase, 16);
    cp16(sB0 + 16, bbase + 4, 16);
    cp_commit();

    float acc[8][4];
#pragma unroll
    for (int m = 0; m < 8; m++)
#pragma unroll
        for (int n = 0; n < 4; n++) acc[m][n] = 0.f;

    for (int kt = 0; kt < NT; kt++) {
        if (kt + 1 < NT) {
            int k0 = (kt + 1) * 16;
            uint32_t dA = ((kt + 1) & 1) ? sA1 : sA0;
            uint32_t dB = ((kt + 1) & 1) ? sB1 : sB0;
            cp16(dA, abase + k0, aok);
            const float* bp = bbase + (size_t)k0 * CC;
            cp16(dB, bp, 16);
            cp16(dB + 16, bp + 4, 16);
            cp_commit();
            cp_wait1();
        } else {
            cp_wait0();
        }
        __syncthreads();

        const float* Ab = As[kt & 1];
        const float* Bb = Bs[kt & 1];
#pragma unroll
        for (int kk = 0; kk < 16; kk++) {
            float4 b4 = *(const float4*)&Bb[kk * 128 + tx * 4];
            float a[8];
#pragma unroll
            for (int m = 0; m < 8; m++) a[m] = Ab[(ty * 8 + m) * 16 + kk];
#pragma unroll
            for (int m = 0; m < 8; m++) {
                acc[m][0] += a[m] * b4.x;
                acc[m][1] += a[m] * b4.y;
                acc[m][2] += a[m] * b4.z;
                acc[m][3] += a[m] * b4.w;
            }
        }
        __syncthreads();
    }

    float4 bb = *(const float4*)(bias + tx * 4);
#pragma unroll
    for (int m = 0; m < 8; m++) {
        int grow = row0 + ty * 8 + m;
        if (grow < Nrows) {
            float4 v = make_float4(acc[m][0] + bb.x, acc[m][1] + bb.y,
                                   acc[m][2] + bb.z, acc[m][3] + bb.w);
            *(float4*)(out + (size_t)grow * CC + tx * 4) = v;
        }
    }
}

// ---------------- per-node-head attention logits ----------------
__global__ void alpha1_kernel(const float* __restrict__ Hm, const float* __restrict__ att,
                              float* __restrict__ out, int N) {
    __shared__ float a[CC];
    if (threadIdx.x < CC) a[threadIdx.x] = att[threadIdx.x];
    __syncthreads();
    int idx = blockIdx.x * blockDim.x + threadIdx.x;
    if (idx >= N * HH) return;
    int h = idx & 7, n = idx >> 3;
    const float4* hp = (const float4*)(Hm + (size_t)n * CC + h * DD);
    const float4* ap = (const float4*)(a + h * DD);
    float s = 0.f;
#pragma unroll
    for (int j = 0; j < 4; j++) {
        float4 x = hp[j], w = ap[j];
        s += x.x * w.x + x.y * w.y + x.z * w.z + x.w * w.w;
    }
    out[idx] = s;
}

__global__ void alpha3_kernel(const float* __restrict__ Hm,
                              const float* __restrict__ a1, const float* __restrict__ a2,
                              const float* __restrict__ a3,
                              float* __restrict__ o1, float* __restrict__ o2,
                              float* __restrict__ o3, int N) {
    __shared__ float s1[CC], s2[CC], s3[CC];
    if (threadIdx.x < CC) {
        s1[threadIdx.x] = a1[threadIdx.x];
        s2[threadIdx.x] = a2[threadIdx.x];
        s3[threadIdx.x] = a3[threadIdx.x];
    }
    __syncthreads();
    int idx = blockIdx.x * blockDim.x + threadIdx.x;
    if (idx >= N * HH) return;
    int h = idx & 7, n = idx >> 3;
    const float4* hp = (const float4*)(Hm + (size_t)n * CC + h * DD);
    const float4* p1 = (const float4*)(s1 + h * DD);
    const float4* p2 = (const float4*)(s2 + h * DD);
    const float4* p3 = (const float4*)(s3 + h * DD);
    float r1 = 0.f, r2 = 0.f, r3 = 0.f;
#pragma unroll
    for (int j = 0; j < 4; j++) {
        float4 x = hp[j];
        float4 w1 = p1[j], w2 = p2[j], w3 = p3[j];
        r1 += x.x * w1.x + x.y * w1.y + x.z * w1.z + x.w * w1.w;
        r2 += x.x * w2.x + x.y * w2.y + x.z * w2.z + x.w * w2.w;
        r3 += x.x * w3.x + x.y * w3.y + x.z * w3.z + x.w * w3.w;
    }
    o1[idx] = r1; o2[idx] = r2; o3[idx] = r3;
}

// ---------------- single-pass fused edge softmax + aggregation (warp per dst) ----------------
__global__ void edge_fused_kernel(const int* __restrict__ rowptr,
                                  const int* __restrict__ srcs,
                                  const float* __restrict__ as,
                                  const float* __restrict__ ad,
                                  const float* __restrict__ Hsrc,
                                  float* __restrict__ outp) {
    int warp = threadIdx.x >> 5;
    int lane = threadIdx.x & 31;
    int dst = blockIdx.x * 8 + warp;
    if (dst >= NP) return;

    int base = rowptr[dst];
    int deg = rowptr[dst + 1] - base;

    float* ow = outp + (size_t)dst * CC;
    if (deg == 0) {
        *(float4*)(ow + lane * 4) = make_float4(0.f, 0.f, 0.f, 0.f);
        return;
    }

    int myh = lane >> 2;
    float advh = ad[dst * HH + myh];

    float4 acc0 = make_float4(0.f, 0.f, 0.f, 0.f);
    float4 acc1 = make_float4(0.f, 0.f, 0.f, 0.f);
    float d0 = 0.f, d1 = 0.f;
    int i = 0;
    for (; i + 2 <= deg; i += 2) {
        int s0 = srcs[base + i];
        int s1 = srcs[base + i + 1];
        float v0 = as[s0 * HH + myh] + advh;
        float v1 = as[s1 * HH + myh] + advh;
        v0 = (v0 >= 0.f) ? v0 : 0.2f * v0;
        v1 = (v1 >= 0.f) ? v1 : 0.2f * v1;
        float e0 = __expf(v0);
        float e1 = __expf(v1);
        float4 h0 = *(const float4*)(Hsrc + (size_t)s0 * CC + lane * 4);
        float4 h1 = *(const float4*)(Hsrc + (size_t)s1 * CC + lane * 4);
        d0 += e0; d1 += e1;
        acc0.x += e0 * h0.x; acc0.y += e0 * h0.y;
        acc0.z += e0 * h0.z; acc0.w += e0 * h0.w;
        acc1.x += e1 * h1.x; acc1.y += e1 * h1.y;
        acc1.z += e1 * h1.z; acc1.w += e1 * h1.w;
    }
    if (i < deg) {
        int s0 = srcs[base + i];
        float v0 = as[s0 * HH + myh] + advh;
        v0 = (v0 >= 0.f) ? v0 : 0.2f * v0;
        float e0 = __expf(v0);
        float4 h0 = *(const float4*)(Hsrc + (size_t)s0 * CC + lane * 4);
        d0 += e0;
        acc0.x += e0 * h0.x; acc0.y += e0 * h0.y;
        acc0.z += e0 * h0.z; acc0.w += e0 * h0.w;
    }
    float inv = 1.f / (d0 + d1);
    float4 v = make_float4(fmaxf((acc0.x + acc1.x) * inv, 0.f),
                           fmaxf((acc0.y + acc1.y) * inv, 0.f),
                           fmaxf((acc0.z + acc1.z) * inv, 0.f),
                           fmaxf((acc0.w + acc1.w) * inv, 0.f));
    *(float4*)(ow + lane * 4) = v;
}

// ---------------- semantic attention: double-buffered GEMM + tanh.approx epilogue ----------------
__global__ __launch_bounds__(256) void semantic_kernel(const float* __restrict__ kW,
                                                       const float* __restrict__ kb,
                                                       const float* __restrict__ q) {
    const float* A = g_out01 + (size_t)blockIdx.y * NP * CC;
    __shared__ float As[2][64 * 16];
    __shared__ float Bs[2][16 * 128];
    __shared__ float red[256];
    int tid = threadIdx.x;
    int tx = tid & 31, ty = tid >> 5;
    int row0 = blockIdx.x * 64;

    int lar = tid >> 2;
    int lak = (tid & 3) * 4;
    int lbk = tid >> 4;
    int lbc = (tid & 15) * 8;

    int garow = row0 + lar;
    int aok = (garow < NP) ? 16 : 0;
    const float* abase = A + (size_t)(aok ? garow : 0) * CC + lak;

    uint32_t sA0 = (uint32_t)__cvta_generic_to_shared(&As[0][lar * 16 + lak]);
    uint32_t sA1 = (uint32_t)__cvta_generic_to_shared(&As[1][lar * 16 + lak]);
    uint32_t sB0 = (uint32_t)__cvta_generic_to_shared(&Bs[0][lbk * 128 + lbc]);
    uint32_t sB1 = (uint32_t)__cvta_generic_to_shared(&Bs[1][lbk * 128 + lbc]);
    const float* bbase = kW + (size_t)lbk * CC + lbc;

    const int NT = CC / 16;

    cp16(sA0, abase, aok);
    cp16(sB0, bbase, 16);
    cp16(sB0 + 16, bbase + 4, 16);
    cp_commit();

    float acc[8][4];
#pragma unroll
    for (int m = 0; m < 8; m++)
#pragma unroll
        for (int n = 0; n < 4; n++) acc[m][n] = 0.f;

    for (int kt = 0; kt < NT; kt++) {
        if (kt + 1 < NT) {
            int k0 = (kt + 1) * 16;
            uint32_t dA = ((kt + 1) & 1) ? sA1 : sA0;
            uint32_t dB = ((kt + 1) & 1) ? sB1 : sB0;
            cp16(dA, abase + k0, aok);
            const float* bp = bbase + (size_t)k0 * CC;
            cp16(dB, bp, 16);
            cp16(dB + 16, bp + 4, 16);
            cp_commit();
            cp_wait1();
        } else {
            cp_wait0();
        }
        __syncthreads();

        const float* Ab = As[kt & 1];
        const float* Bb = Bs[kt & 1];
#pragma unroll
        for (int kk = 0; kk < 16; kk++) {
            float4 b4 = *(const float4*)&Bb[kk * 128 + tx * 4];
            float a[8];
#pragma unroll
            for (int m = 0; m < 8; m++) a[m] = Ab[(ty * 8 + m) * 16 + kk];
#pragma unroll
            for (int m = 0; m < 8; m++) {
                acc[m][0] += a[m] * b4.x;
                acc[m][1] += a[m] * b4.y;
                acc[m][2] += a[m] * b4.z;
                acc[m][3] += a[m] * b4.w;
            }
        }
        __syncthreads();
    }

    float4 kbv = *(const float4*)(kb + tx * 4);
    float4 qv = *(const float4*)(q + tx * 4);
    float part = 0.f;
#pragma unroll
    for (int m = 0; m < 8; m++) {
        int grow = row0 + ty * 8 + m;
        if (grow < NP) {
            part += tanh_fast(acc[m][0] + kbv.x) * qv.x;
            part += tanh_fast(acc[m][1] + kbv.y) * qv.y;
            part += tanh_fast(acc[m][2] + kbv.z) * qv.z;
            part += tanh_fast(acc[m][3] + kbv.w) * qv.w;
        }
    }
    red[tid] = part;
    __syncthreads();
    for (int s = 128; s > 0; s >>= 1) {
        if (tid < s) red[tid] += red[tid + s];
        __syncthreads();
    }
    if (tid == 0) atomicAdd(&g_wsum[blockIdx.y], red[0]);
}

__global__ void beta_kernel() {
    float w0 = g_wsum[0] / (float)NP;
    float w1 = g_wsum[1] / (float)NP;
    float m = fmaxf(w0, w1);
    float e0 = expf(w0 - m), e1 = expf(w1 - m);
    float s = e0 + e1;
    g_beta[0] = e0 / s;
    g_beta[1] = e1 / s;
}

// ---------------- per-channel stats ----------------
#define STAT_ROWS 512
__global__ void stats_kernel() {
    int c = threadIdx.x;
    float b0 = g_beta[0], b1 = g_beta[1];
    const float* o0 = g_out01;
    const float* o1 = g_out01 + (size_t)NP * CC;
    int r0 = blockIdx.x * STAT_ROWS;
    int r1 = r0 + STAT_ROWS; if (r1 > NP) r1 = NP;
    float s1 = 0.f, s2 = 0.f;
    for (int r = r0; r < r1; r++) {
        float v = b0 * o0[(size_t)r * CC + c] + b1 * o1[(size_t)r * CC + c];
        s1 += v;
        s2 += v * v;
    }
    atomicAdd(&g_S1[c], s1);
    atomicAdd(&g_S2[c], s2);
}

__global__ void normparam_kernel(const float* __restrict__ norm_w,
                                 const float* __restrict__ norm_b,
                                 const float* __restrict__ norm_ms) {
    int c = threadIdx.x;
    float mean = g_S1[c] / (float)NP;
    float eo2 = g_S2[c] / (float)NP;
    float mm = mean * norm_ms[c];
    float var = eo2 - 2.f * mm * mean + mm * mm;
    float A = norm_w[c] * rsqrtf(var + EPSV);
    g_nA[c] = A;
    g_nB[c] = norm_b[c] - mm * A;
}

// ---------------- fused normalize + classifier ----------------
__global__ void final_kernel(const float* __restrict__ linW,
                             const float* __restrict__ linb,
                             float* __restrict__ y) {
    __shared__ float rowbuf[16][CC];
    __shared__ float lw[CC * OUTC];
    __shared__ float lb[OUTC];
    int tid = threadIdx.x;
    for (int i = tid; i < CC * OUTC; i += 256) lw[i] = linW[i];
    if (tid < OUTC) lb[tid] = linb[tid];
    float b0 = g_beta[0], b1 = g_beta[1];
    const float* o0 = g_out01;
    const float* o1 = g_out01 + (size_t)NP * CC;
    int nrow0 = blockIdx.x * 16;
#pragma unroll
    for (int j = 0; j < 8; j++) {
        int i = tid + j * 256;
        int r = i >> 7, c = i & 127;
        int gr = nrow0 + r;
        float v = 0.f;
        if (gr < NP) {
            v = b0 * o0[(size_t)gr * CC + c] + b1 * o1[(size_t)gr * CC + c];
            v = v * g_nA[c] + g_nB[c];
        }
        rowbuf[r][c] = v;
    }
    __syncthreads();
    int r = tid >> 4, o = tid & 15;
    int gr = nrow0 + r;
    if (gr < NP) {
        float s = lb[o];
#pragma unroll
        for (int c = 0; c < CC; c++) s += rowbuf[r][c] * lw[c * OUTC + o];
        y[(size_t)gr * OUTC + o] = s;
    }
}

// ---------------- launch ----------------
extern "C" void kernel_launch(void* const* d_in, const int* in_sizes, int n_in,
                              void* d_out, int out_size) {
    const float* x_author = (const float*)d_in[0];
    const float* x_paper  = (const float*)d_in[1];
    const float* W_a      = (const float*)d_in[2];
    const float* b_a      = (const float*)d_in[3];
    const float* W_p      = (const float*)d_in[4];
    const float* b_p      = (const float*)d_in[5];
    const float* att_src_ap = (const float*)d_in[6];
    const float* att_dst_ap = (const float*)d_in[7];
    const float* att_src_pp = (const float*)d_in[8];
    const float* att_dst_pp = (const float*)d_in[9];
    const float* k_W      = (const float*)d_in[10];
    const float* k_b      = (const float*)d_in[11];
    const float* q        = (const float*)d_in[12];
    const float* norm_w   = (const float*)d_in[13];
    const float* norm_b   = (const float*)d_in[14];
    const float* norm_ms  = (const float*)d_in[15];
    const float* lin_W    = (const float*)d_in[16];
    const float* lin_b    = (const float*)d_in[17];
    const int*   edge_ap  = (const int*)d_in[18];
    const int*   edge_pp  = (const int*)d_in[19];
    float* y = (float*)d_out;

    float *p_h_a, *p_h_p, *p_as_ap, *p_ad_ap, *p_as_pp, *p_ad_pp, *p_out;
    int *p_rowptr, *p_srcs;
    cudaGetSymbolAddress((void**)&p_h_a, g_h_a);
    cudaGetSymbolAddress((void**)&p_h_p, g_h_p);
    cudaGetSymbolAddress((void**)&p_as_ap, g_as_ap);
    cudaGetSymbolAddress((void**)&p_ad_ap, g_ad_ap);
    cudaGetSymbolAddress((void**)&p_as_pp, g_as_pp);
    cudaGetSymbolAddress((void**)&p_ad_pp, g_ad_pp);
    cudaGetSymbolAddress((void**)&p_rowptr, g_rowptr);
    cudaGetSymbolAddress((void**)&p_srcs, g_srcs);
    cudaGetSymbolAddress((void**)&p_out, g_out01);

    // 0. init
    init_kernel<<<128, 256>>>();

    // 1. CSR build (both edge types)
    hist_kernel<<<(2 * EE + 255) / 256, 256>>>(edge_ap, edge_pp);
    scan_kernel<<<2, SCAN_T>>>();
    scatter_kernel<<<(2 * EE + 255) / 256, 256>>>(edge_ap, edge_pp);

    // 2. projections (double-buffered)
    gemm_proj_kernel<FA><<<(NA + 63) / 64, 256>>>(x_author, W_a, b_a, p_h_a, NA);
    gemm_proj_kernel<FP><<<(NP + 63) / 64, 256>>>(x_paper, W_p, b_p, p_h_p, NP);

    // 3. attention logits per node
    alpha1_kernel<<<(NA * HH + 255) / 256, 256>>>(p_h_a, att_src_ap, p_as_ap, NA);
    alpha3_kernel<<<(NP * HH + 255) / 256, 256>>>(p_h_p, att_dst_ap, att_src_pp, att_dst_pp,
                                                  p_ad_ap, p_as_pp, p_ad_pp, NP);

    // 4. single-pass fused edge softmax + aggregation
    edge_fused_kernel<<<(NP + 7) / 8, 256>>>(p_rowptr, p_srcs,
                                             p_as_ap, p_ad_ap, p_h_a, p_out);
    edge_fused_kernel<<<(NP + 7) / 8, 256>>>(p_rowptr + (NP + 1), p_srcs + EE,
                                             p_as_pp, p_ad_pp, p_h_p,
                                             p_out + (size_t)NP * CC);

    // 5. semantic attention
    dim3 sgrid((NP + 63) / 64, 2);
    semantic_kernel<<<sgrid, 256>>>(k_W, k_b, q);
    beta_kernel<<<1, 1>>>();

    // 6. GraphNorm stats + params
    stats_kernel<<<(NP + STAT_ROWS - 1) / STAT_ROWS, CC>>>();
    normparam_kernel<<<1, CC>>>(norm_w, norm_b, norm_ms);

    // 7. normalize + classify
    final_kernel<<<(NP + 15) / 16, 256>>>(lin_W, lin_b, y);
}

// round 5
// speedup vs baseline: 1.4063x; 1.2805x over previous
#include <cuda_runtime.h>
#include <math.h>
#include <stdint.h>

#define NA 50000
#define NP 50000
#define EE 600000
#define HH 8
#define DD 16
#define CC 128
#define OUTC 16
#define FA 256
#define FP 128
#define EPSV 1e-5f

// ---------------- device scratch ----------------
__device__ float    g_h_a[(size_t)NA * CC];
__device__ float    g_h_p[(size_t)NP * CC];
__device__ float    g_as_ap[NA * HH];
__device__ float    g_ad_ap[NP * HH];
__device__ float    g_as_pp[NP * HH];
__device__ float    g_ad_pp[NP * HH];
__device__ int      g_cnt[2 * NP];
__device__ int      g_cur[2 * NP];
__device__ int      g_rowptr[2 * (NP + 1)];
__device__ int      g_srcs[2 * (size_t)EE];
__device__ float    g_out01[2 * (size_t)NP * CC]; // relu-applied
__device__ float    g_wsum[2];
__device__ float    g_beta[2];
__device__ float    g_S1[CC];
__device__ float    g_S2[CC];
__device__ float    g_nA[CC];
__device__ float    g_nB[CC];

// ---------------- helpers ----------------
__device__ __forceinline__ float tanh_fast(float x) {
    float y;
    asm("tanh.approx.f32 %0, %1;" : "=f"(y) : "f"(x));
    return y;
}
__device__ __forceinline__ uint32_t f2tf(float x) {
    uint32_t r;
    asm("cvt.rna.tf32.f32 %0, %1;" : "=r"(r) : "f"(x));
    return r;
}
__device__ __forceinline__ void mma_tf32(float* c, const uint32_t* a,
                                         uint32_t b0, uint32_t b1) {
    asm("mma.sync.aligned.m16n8k8.row.col.f32.tf32.tf32.f32 "
        "{%0,%1,%2,%3},{%4,%5,%6,%7},{%8,%9},{%0,%1,%2,%3};"
        : "+f"(c[0]), "+f"(c[1]), "+f"(c[2]), "+f"(c[3])
        : "r"(a[0]), "r"(a[1]), "r"(a[2]), "r"(a[3]), "r"(b0), "r"(b1));
}
__device__ __forceinline__ void cp16(uint32_t dst, const void* src, int sz) {
    asm volatile("cp.async.ca.shared.global [%0], [%1], 16, %2;"
                 :: "r"(dst), "l"(src), "r"(sz));
}
__device__ __forceinline__ void cp_commit() { asm volatile("cp.async.commit_group;"); }
__device__ __forceinline__ void cp_wait1()  { asm volatile("cp.async.wait_group 1;"); }
__device__ __forceinline__ void cp_wait0()  { asm volatile("cp.async.wait_group 0;"); }

#define APITCH 20
#define BPITCH 136

// ---------------- init ----------------
__global__ void init_kernel() {
    int idx = blockIdx.x * blockDim.x + threadIdx.x;
    int stride = gridDim.x * blockDim.x;
    for (int i = idx; i < 2 * NP; i += stride) g_cnt[i] = 0;
    if (idx < CC) { g_S1[idx] = 0.f; g_S2[idx] = 0.f; }
    if (idx < 2)  g_wsum[idx] = 0.f;
}

// ---------------- CSR build ----------------
__global__ void hist_kernel(const int* __restrict__ e_ap, const int* __restrict__ e_pp) {
    int idx = blockIdx.x * blockDim.x + threadIdx.x;
    if (idx >= 2 * EE) return;
    int t = (idx >= EE);
    int e = idx - t * EE;
    const int* ed = t ? e_pp : e_ap;
    int dst = ed[EE + e];
    atomicAdd(&g_cnt[t * NP + dst], 1);
}

#define SCAN_T 1024
#define SCAN_CHUNK 49
__global__ void scan_kernel() {
    int t = blockIdx.x;
    int tid = threadIdx.x;
    const int* cnt = g_cnt + t * NP;
    int* rowptr = g_rowptr + t * (NP + 1);
    int* cur = g_cur + t * NP;

    int lo = tid * SCAN_CHUNK;
    int hi = lo + SCAN_CHUNK; if (hi > NP) hi = NP;
    int tsum = 0;
    for (int i = lo; i < hi; i++) tsum += cnt[i];

    __shared__ int sh[SCAN_T];
    sh[tid] = tsum;
    __syncthreads();
    for (int off = 1; off < SCAN_T; off <<= 1) {
        int v = (tid >= off) ? sh[tid - off] : 0;
        __syncthreads();
        sh[tid] += v;
        __syncthreads();
    }
    int running = sh[tid] - tsum;
    for (int i = lo; i < hi; i++) {
        rowptr[i] = running;
        cur[i] = running;
        running += cnt[i];
    }
    if (tid == 0) rowptr[NP] = EE;
}

__global__ void scatter_kernel(const int* __restrict__ e_ap, const int* __restrict__ e_pp) {
    int idx = blockIdx.x * blockDim.x + threadIdx.x;
    if (idx >= 2 * EE) return;
    int t = (idx >= EE);
    int e = idx - t * EE;
    const int* ed = t ? e_pp : e_ap;
    int src = ed[e];
    int dst = ed[EE + e];
    int pos = atomicAdd(&g_cur[t * NP + dst], 1);
    g_srcs[(size_t)t * EE + pos] = src;
}

// ---------------- tf32 tensor-core GEMM: out[N,128] = X[N,KDIM] @ W[KDIM,128] + bias ----
// BM=128 (8 warps x m16), BN=128 (16 n-tiles), BK=16, cp.async double buffer
template <int KDIM>
__global__ __launch_bounds__(256) void gemm_mma_kernel(
        const float* __restrict__ X, const float* __restrict__ W,
        const float* __restrict__ bias, float* __restrict__ out, int Nrows) {
    __shared__ float As[2][128 * APITCH];
    __shared__ float Bs[2][16 * BPITCH];
    int tid = threadIdx.x, w = tid >> 5, lane = tid & 31;
    int row0 = blockIdx.x * 128;

    // loader mapping
    int arow = tid >> 1, ak = (tid & 1) * 8;
    int brow = tid >> 4, bc = (tid & 15) * 8;
    int garow = row0 + arow;
    int aok = (garow < Nrows) ? 16 : 0;
    const float* abase = X + (size_t)(aok ? garow : 0) * KDIM + ak;
    const float* bbase = W + (size_t)brow * CC + bc;

    uint32_t dA0 = (uint32_t)__cvta_generic_to_shared(&As[0][arow * APITCH + ak]);
    uint32_t dA1 = (uint32_t)__cvta_generic_to_shared(&As[1][arow * APITCH + ak]);
    uint32_t dB0 = (uint32_t)__cvta_generic_to_shared(&Bs[0][brow * BPITCH + bc]);
    uint32_t dB1 = (uint32_t)__cvta_generic_to_shared(&Bs[1][brow * BPITCH + bc]);

    const int NT = KDIM / 16;
    cp16(dA0, abase, aok); cp16(dA0 + 16, abase + 4, aok);
    cp16(dB0, bbase, 16);  cp16(dB0 + 16, bbase + 4, 16);
    cp_commit();

    float acc[16][4];
#pragma unroll
    for (int nt = 0; nt < 16; nt++)
#pragma unroll
        for (int j = 0; j < 4; j++) acc[nt][j] = 0.f;

    int g = lane >> 2, t4 = lane & 3;

    for (int kt = 0; kt < NT; kt++) {
        if (kt + 1 < NT) {
            uint32_t dA = ((kt + 1) & 1) ? dA1 : dA0;
            uint32_t dB = ((kt + 1) & 1) ? dB1 : dB0;
            const float* ap = abase + (kt + 1) * 16;
            const float* bp = bbase + (size_t)(kt + 1) * 16 * CC;
            cp16(dA, ap, aok); cp16(dA + 16, ap + 4, aok);
            cp16(dB, bp, 16);  cp16(dB + 16, bp + 4, 16);
            cp_commit();
            cp_wait1();
        } else {
            cp_wait0();
        }
        __syncthreads();

        const float* Ab = As[kt & 1];
        const float* Bb = Bs[kt & 1];

        uint32_t afr[2][4];
#pragma unroll
        for (int s = 0; s < 2; s++) {
            int k = s * 8 + t4;
            afr[s][0] = f2tf(Ab[(w * 16 + g) * APITCH + k]);
            afr[s][1] = f2tf(Ab[(w * 16 + g + 8) * APITCH + k]);
            afr[s][2] = f2tf(Ab[(w * 16 + g) * APITCH + k + 4]);
            afr[s][3] = f2tf(Ab[(w * 16 + g + 8) * APITCH + k + 4]);
        }
#pragma unroll
        for (int nt = 0; nt < 16; nt++) {
            int col = nt * 8 + g;
#pragma unroll
            for (int s = 0; s < 2; s++) {
                int kr = s * 8 + t4;
                uint32_t b0 = f2tf(Bb[kr * BPITCH + col]);
                uint32_t b1 = f2tf(Bb[(kr + 4) * BPITCH + col]);
                mma_tf32(acc[nt], afr[s], b0, b1);
            }
        }
        __syncthreads();
    }

    int t2 = t4 * 2;
    int r1 = row0 + w * 16 + g;
    int r2 = r1 + 8;
#pragma unroll
    for (int nt = 0; nt < 16; nt++) {
        int col = nt * 8 + t2;
        float2 bb = *(const float2*)(bias + col);
        if (r1 < Nrows) {
            float2 v = make_float2(acc[nt][0] + bb.x, acc[nt][1] + bb.y);
            *(float2*)(out + (size_t)r1 * CC + col) = v;
        }
        if (r2 < Nrows) {
            float2 v = make_float2(acc[nt][2] + bb.x, acc[nt][3] + bb.y);
            *(float2*)(out + (size_t)r2 * CC + col) = v;
        }
    }
}

// ---------------- semantic: tf32 GEMM + tanh.approx epilogue reduce ----------------
__global__ __launch_bounds__(256) void semantic_mma_kernel(
        const float* __restrict__ kW, const float* __restrict__ kb,
        const float* __restrict__ q) {
    const float* X = g_out01 + (size_t)blockIdx.y * NP * CC;
    __shared__ float As[2][128 * APITCH];
    __shared__ float Bs[2][16 * BPITCH];
    __shared__ float red[8];
    int tid = threadIdx.x, w = tid >> 5, lane = tid & 31;
    int row0 = blockIdx.x * 128;

    int arow = tid >> 1, ak = (tid & 1) * 8;
    int brow = tid >> 4, bc = (tid & 15) * 8;
    int garow = row0 + arow;
    int aok = (garow < NP) ? 16 : 0;
    const float* abase = X + (size_t)(aok ? garow : 0) * CC + ak;
    const float* bbase = kW + (size_t)brow * CC + bc;

    uint32_t dA0 = (uint32_t)__cvta_generic_to_shared(&As[0][arow * APITCH + ak]);
    uint32_t dA1 = (uint32_t)__cvta_generic_to_shared(&As[1][arow * APITCH + ak]);
    uint32_t dB0 = (uint32_t)__cvta_generic_to_shared(&Bs[0][brow * BPITCH + bc]);
    uint32_t dB1 = (uint32_t)__cvta_generic_to_shared(&Bs[1][brow * BPITCH + bc]);

    const int NT = CC / 16;
    cp16(dA0, abase, aok); cp16(dA0 + 16, abase + 4, aok);
    cp16(dB0, bbase, 16);  cp16(dB0 + 16, bbase + 4, 16);
    cp_commit();

    float acc[16][4];
#pragma unroll
    for (int nt = 0; nt < 16; nt++)
#pragma unroll
        for (int j = 0; j < 4; j++) acc[nt][j] = 0.f;

    int g = lane >> 2, t4 = lane & 3;

    for (int kt = 0; kt < NT; kt++) {
        if (kt + 1 < NT) {
            uint32_t dA = ((kt + 1) & 1) ? dA1 : dA0;
            uint32_t dB = ((kt + 1) & 1) ? dB1 : dB0;
            const float* ap = abase + (kt + 1) * 16;
            const float* bp = bbase + (size_t)(kt + 1) * 16 * CC;
            cp16(dA, ap, aok); cp16(dA + 16, ap + 4, aok);
            cp16(dB, bp, 16);  cp16(dB + 16, bp + 4, 16);
            cp_commit();
            cp_wait1();
        } else {
            cp_wait0();
        }
        __syncthreads();

        const float* Ab = As[kt & 1];
        const float* Bb = Bs[kt & 1];

        uint32_t afr[2][4];
#pragma unroll
        for (int s = 0; s < 2; s++) {
            int k = s * 8 + t4;
            afr[s][0] = f2tf(Ab[(w * 16 + g) * APITCH + k]);
            afr[s][1] = f2tf(Ab[(w * 16 + g + 8) * APITCH + k]);
            afr[s][2] = f2tf(Ab[(w * 16 + g) * APITCH + k + 4]);
            afr[s][3] = f2tf(Ab[(w * 16 + g + 8) * APITCH + k + 4]);
        }
#pragma unroll
        for (int nt = 0; nt < 16; nt++) {
            int col = nt * 8 + g;
#pragma unroll
            for (int s = 0; s < 2; s++) {
                int kr = s * 8 + t4;
                uint32_t b0 = f2tf(Bb[kr * BPITCH + col]);
                uint32_t b1 = f2tf(Bb[(kr + 4) * BPITCH + col]);
                mma_tf32(acc[nt], afr[s], b0, b1);
            }
        }
        __syncthreads();
    }

    int t2 = t4 * 2;
    int r1 = row0 + w * 16 + g;
    int r2 = r1 + 8;
    float part = 0.f;
#pragma unroll
    for (int nt = 0; nt < 16; nt++) {
        int col = nt * 8 + t2;
        float2 kb2 = *(const float2*)(kb + col);
        float2 q2 = *(const float2*)(q + col);
        if (r1 < NP)
            part += tanh_fast(acc[nt][0] + kb2.x) * q2.x
                  + tanh_fast(acc[nt][1] + kb2.y) * q2.y;
        if (r2 < NP)
            part += tanh_fast(acc[nt][2] + kb2.x) * q2.x
                  + tanh_fast(acc[nt][3] + kb2.y) * q2.y;
    }
#pragma unroll
    for (int o = 16; o; o >>= 1) part += __shfl_xor_sync(0xFFFFFFFFu, part, o);
    if (lane == 0) red[w] = part;
    __syncthreads();
    if (tid == 0) {
        float s = 0.f;
#pragma unroll
        for (int i = 0; i < 8; i++) s += red[i];
        atomicAdd(&g_wsum[blockIdx.y], s);
    }
}

// ---------------- per-node-head attention logits ----------------
__global__ void alpha1_kernel(const float* __restrict__ Hm, const float* __restrict__ att,
                              float* __restrict__ out, int N) {
    __shared__ float a[CC];
    if (threadIdx.x < CC) a[threadIdx.x] = att[threadIdx.x];
    __syncthreads();
    int idx = blockIdx.x * blockDim.x + threadIdx.x;
    if (idx >= N * HH) return;
    int h = idx & 7, n = idx >> 3;
    const float4* hp = (const float4*)(Hm + (size_t)n * CC + h * DD);
    const float4* ap = (const float4*)(a + h * DD);
    float s = 0.f;
#pragma unroll
    for (int j = 0; j < 4; j++) {
        float4 x = hp[j], w = ap[j];
        s += x.x * w.x + x.y * w.y + x.z * w.z + x.w * w.w;
    }
    out[idx] = s;
}

__global__ void alpha3_kernel(const float* __restrict__ Hm,
                              const float* __restrict__ a1, const float* __restrict__ a2,
                              const float* __restrict__ a3,
                              float* __restrict__ o1, float* __restrict__ o2,
                              float* __restrict__ o3, int N) {
    __shared__ float s1[CC], s2[CC], s3[CC];
    if (threadIdx.x < CC) {
        s1[threadIdx.x] = a1[threadIdx.x];
        s2[threadIdx.x] = a2[threadIdx.x];
        s3[threadIdx.x] = a3[threadIdx.x];
    }
    __syncthreads();
    int idx = blockIdx.x * blockDim.x + threadIdx.x;
    if (idx >= N * HH) return;
    int h = idx & 7, n = idx >> 3;
    const float4* hp = (const float4*)(Hm + (size_t)n * CC + h * DD);
    const float4* p1 = (const float4*)(s1 + h * DD);
    const float4* p2 = (const float4*)(s2 + h * DD);
    const float4* p3 = (const float4*)(s3 + h * DD);
    float r1 = 0.f, r2 = 0.f, r3 = 0.f;
#pragma unroll
    for (int j = 0; j < 4; j++) {
        float4 x = hp[j];
        float4 w1 = p1[j], w2 = p2[j], w3 = p3[j];
        r1 += x.x * w1.x + x.y * w1.y + x.z * w1.z + x.w * w1.w;
        r2 += x.x * w2.x + x.y * w2.y + x.z * w2.z + x.w * w2.w;
        r3 += x.x * w3.x + x.y * w3.y + x.z * w3.z + x.w * w3.w;
    }
    o1[idx] = r1; o2[idx] = r2; o3[idx] = r3;
}

// ---------------- fused edge softmax + aggregation, staged via smem ----------------
__global__ void edge_fused_kernel(const int* __restrict__ rowptr,
                                  const int* __restrict__ srcs,
                                  const float* __restrict__ as,
                                  const float* __restrict__ ad,
                                  const float* __restrict__ Hsrc,
                                  float* __restrict__ outp) {
    __shared__ int   sh_s[8][32];
    __shared__ float sh_e[8][32][8];
    int warp = threadIdx.x >> 5;
    int lane = threadIdx.x & 31;
    int dst = blockIdx.x * 8 + warp;
    if (dst >= NP) return;

    int base = rowptr[dst];
    int deg = rowptr[dst + 1] - base;

    float* ow = outp + (size_t)dst * CC;
    if (deg == 0) {
        *(float4*)(ow + lane * 4) = make_float4(0.f, 0.f, 0.f, 0.f);
        return;
    }

    // dst logits for all heads (broadcast, L1-resident)
    float4 ad0 = *(const float4*)(ad + dst * HH);
    float4 ad1 = *(const float4*)(ad + dst * HH + 4);
    float advs[8] = {ad0.x, ad0.y, ad0.z, ad0.w, ad1.x, ad1.y, ad1.z, ad1.w};

    int myh = lane >> 2;
    float4 acc = make_float4(0.f, 0.f, 0.f, 0.f);
    float denom = 0.f;

    for (int chunk = 0; chunk < deg; chunk += 32) {
        int n = min(32, deg - chunk);
        if (lane < n) {
            int s = srcs[base + chunk + lane];
            sh_s[warp][lane] = s;
            float4 a0 = *(const float4*)(as + s * HH);
            float4 a1 = *(const float4*)(as + s * HH + 4);
            float al[8] = {a0.x, a0.y, a0.z, a0.w, a1.x, a1.y, a1.z, a1.w};
            float e[8];
#pragma unroll
            for (int h = 0; h < 8; h++) {
                float v = al[h] + advs[h];
                v = (v >= 0.f) ? v : 0.2f * v;
                e[h] = __expf(v);
            }
            *(float4*)&sh_e[warp][lane][0] = make_float4(e[0], e[1], e[2], e[3]);
            *(float4*)&sh_e[warp][lane][4] = make_float4(e[4], e[5], e[6], e[7]);
        }
        __syncwarp();
#pragma unroll 4
        for (int i = 0; i < n; i++) {
            int s = sh_s[warp][i];
            float wgt = sh_e[warp][i][myh];
            float4 hv = *(const float4*)(Hsrc + (size_t)s * CC + lane * 4);
            denom += wgt;
            acc.x += wgt * hv.x; acc.y += wgt * hv.y;
            acc.z += wgt * hv.z; acc.w += wgt * hv.w;
        }
        __syncwarp();
    }
    float inv = 1.f / denom;
    float4 v = make_float4(fmaxf(acc.x * inv, 0.f), fmaxf(acc.y * inv, 0.f),
                           fmaxf(acc.z * inv, 0.f), fmaxf(acc.w * inv, 0.f));
    *(float4*)(ow + lane * 4) = v;
}

__global__ void beta_kernel() {
    float w0 = g_wsum[0] / (float)NP;
    float w1 = g_wsum[1] / (float)NP;
    float m = fmaxf(w0, w1);
    float e0 = expf(w0 - m), e1 = expf(w1 - m);
    float s = e0 + e1;
    g_beta[0] = e0 / s;
    g_beta[1] = e1 / s;
}

// ---------------- per-channel stats ----------------
#define STAT_ROWS 512
__global__ void stats_kernel() {
    int c = threadIdx.x;
    float b0 = g_beta[0], b1 = g_beta[1];
    const float* o0 = g_out01;
    const float* o1 = g_out01 + (size_t)NP * CC;
    int r0 = blockIdx.x * STAT_ROWS;
    int r1 = r0 + STAT_ROWS; if (r1 > NP) r1 = NP;
    float s1 = 0.f, s2 = 0.f;
    for (int r = r0; r < r1; r++) {
        float v = b0 * o0[(size_t)r * CC + c] + b1 * o1[(size_t)r * CC + c];
        s1 += v;
        s2 += v * v;
    }
    atomicAdd(&g_S1[c], s1);
    atomicAdd(&g_S2[c], s2);
}

__global__ void normparam_kernel(const float* __restrict__ norm_w,
                                 const float* __restrict__ norm_b,
                                 const float* __restrict__ norm_ms) {
    int c = threadIdx.x;
    float mean = g_S1[c] / (float)NP;
    float eo2 = g_S2[c] / (float)NP;
    float mm = mean * norm_ms[c];
    float var = eo2 - 2.f * mm * mean + mm * mm;
    float A = norm_w[c] * rsqrtf(var + EPSV);
    g_nA[c] = A;
    g_nB[c] = norm_b[c] - mm * A;
}

// ---------------- fused normalize + classifier ----------------
__global__ void final_kernel(const float* __restrict__ linW,
                             const float* __restrict__ linb,
                             float* __restrict__ y) {
    __shared__ float rowbuf[16][CC];
    __shared__ float lw[CC * OUTC];
    __shared__ float lb[OUTC];
    int tid = threadIdx.x;
    for (int i = tid; i < CC * OUTC; i += 256) lw[i] = linW[i];
    if (tid < OUTC) lb[tid] = linb[tid];
    float b0 = g_beta[0], b1 = g_beta[1];
    const float* o0 = g_out01;
    const float* o1 = g_out01 + (size_t)NP * CC;
    int nrow0 = blockIdx.x * 16;
#pragma unroll
    for (int j = 0; j < 8; j++) {
        int i = tid + j * 256;
        int r = i >> 7, c = i & 127;
        int gr = nrow0 + r;
        float v = 0.f;
        if (gr < NP) {
            v = b0 * o0[(size_t)gr * CC + c] + b1 * o1[(size_t)gr * CC + c];
            v = v * g_nA[c] + g_nB[c];
        }
        rowbuf[r][c] = v;
    }
    __syncthreads();
    int r = tid >> 4, o = tid & 15;
    int gr = nrow0 + r;
    if (gr < NP) {
        float s = lb[o];
#pragma unroll
        for (int c = 0; c < CC; c++) s += rowbuf[r][c] * lw[c * OUTC + o];
        y[(size_t)gr * OUTC + o] = s;
    }
}

// ---------------- launch ----------------
extern "C" void kernel_launch(void* const* d_in, const int* in_sizes, int n_in,
                              void* d_out, int out_size) {
    const float* x_author = (const float*)d_in[0];
    const float* x_paper  = (const float*)d_in[1];
    const float* W_a      = (const float*)d_in[2];
    const float* b_a      = (const float*)d_in[3];
    const float* W_p      = (const float*)d_in[4];
    const float* b_p      = (const float*)d_in[5];
    const float* att_src_ap = (const float*)d_in[6];
    const float* att_dst_ap = (const float*)d_in[7];
    const float* att_src_pp = (const float*)d_in[8];
    const float* att_dst_pp = (const float*)d_in[9];
    const float* k_W      = (const float*)d_in[10];
    const float* k_b      = (const float*)d_in[11];
    const float* q        = (const float*)d_in[12];
    const float* norm_w   = (const float*)d_in[13];
    const float* norm_b   = (const float*)d_in[14];
    const float* norm_ms  = (const float*)d_in[15];
    const float* lin_W    = (const float*)d_in[16];
    const float* lin_b    = (const float*)d_in[17];
    const int*   edge_ap  = (const int*)d_in[18];
    const int*   edge_pp  = (const int*)d_in[19];
    float* y = (float*)d_out;

    float *p_h_a, *p_h_p, *p_as_ap, *p_ad_ap, *p_as_pp, *p_ad_pp, *p_out;
    int *p_rowptr, *p_srcs;
    cudaGetSymbolAddress((void**)&p_h_a, g_h_a);
    cudaGetSymbolAddress((void**)&p_h_p, g_h_p);
    cudaGetSymbolAddress((void**)&p_as_ap, g_as_ap);
    cudaGetSymbolAddress((void**)&p_ad_ap, g_ad_ap);
    cudaGetSymbolAddress((void**)&p_as_pp, g_as_pp);
    cudaGetSymbolAddress((void**)&p_ad_pp, g_ad_pp);
    cudaGetSymbolAddress((void**)&p_rowptr, g_rowptr);
    cudaGetSymbolAddress((void**)&p_srcs, g_srcs);
    cudaGetSymbolAddress((void**)&p_out, g_out01);

    // 0. init
    init_kernel<<<128, 256>>>();

    // 1. CSR build
    hist_kernel<<<(2 * EE + 255) / 256, 256>>>(edge_ap, edge_pp);
    scan_kernel<<<2, SCAN_T>>>();
    scatter_kernel<<<(2 * EE + 255) / 256, 256>>>(edge_ap, edge_pp);

    // 2. projections (tf32 tensor cores)
    gemm_mma_kernel<FA><<<(NA + 127) / 128, 256>>>(x_author, W_a, b_a, p_h_a, NA);
    gemm_mma_kernel<FP><<<(NP + 127) / 128, 256>>>(x_paper, W_p, b_p, p_h_p, NP);

    // 3. attention logits per node
    alpha1_kernel<<<(NA * HH + 255) / 256, 256>>>(p_h_a, att_src_ap, p_as_ap, NA);
    alpha3_kernel<<<(NP * HH + 255) / 256, 256>>>(p_h_p, att_dst_ap, att_src_pp, att_dst_pp,
                                                  p_ad_ap, p_as_pp, p_ad_pp, NP);

    // 4. fused edge softmax + aggregation (smem-staged)
    edge_fused_kernel<<<(NP + 7) / 8, 256>>>(p_rowptr, p_srcs,
                                             p_as_ap, p_ad_ap, p_h_a, p_out);
    edge_fused_kernel<<<(NP + 7) / 8, 256>>>(p_rowptr + (NP + 1), p_srcs + EE,
                                             p_as_pp, p_ad_pp, p_h_p,
                                             p_out + (size_t)NP * CC);

    // 5. semantic attention (tf32 tensor cores)
    dim3 sgrid((NP + 127) / 128, 2);
    semantic_mma_kernel<<<sgrid, 256>>>(k_W, k_b, q);
    beta_kernel<<<1, 1>>>();

    // 6. GraphNorm stats + params
    stats_kernel<<<(NP + STAT_ROWS - 1) / STAT_ROWS, CC>>>();
    normparam_kernel<<<1, CC>>>(norm_w, norm_b, norm_ms);

    // 7. normalize + classify
    final_kernel<<<(NP + 15) / 16, 256>>>(lin_W, lin_b, y);
}

// round 6
// speedup vs baseline: 1.6698x; 1.1874x over previous
#include <cuda_runtime.h>
#include <math.h>
#include <stdint.h>

#define NA 50000
#define NP 50000
#define EE 600000
#define HH 8
#define DD 16
#define CC 128
#define OUTC 16
#define FA 256
#define FP 128
#define EPSV 1e-5f

// ---------------- device scratch ----------------
__device__ float    g_h_a[(size_t)NA * CC];
__device__ float    g_h_p[(size_t)NP * CC];
__device__ float    g_as_ap[NA * HH];
__device__ float    g_ad_ap[NP * HH];
__device__ float    g_as_pp[NP * HH];
__device__ float    g_ad_pp[NP * HH];
__device__ int      g_cnt[2 * NP];
__device__ int      g_cur[2 * NP];
__device__ int      g_rowptr[2 * (NP + 1)];
__device__ int      g_srcs[2 * (size_t)EE];
__device__ float    g_out01[2 * (size_t)NP * CC]; // relu-applied
__device__ float    g_wsum[2];
__device__ float    g_beta[2];
__device__ float    g_Sa[CC], g_Sb[CC], g_Saa[CC], g_Sbb[CC], g_Sab[CC];
__device__ float    g_nA[CC];
__device__ float    g_nB[CC];

// ---------------- helpers ----------------
__device__ __forceinline__ float tanh_fast(float x) {
    float y;
    asm("tanh.approx.f32 %0, %1;" : "=f"(y) : "f"(x));
    return y;
}
__device__ __forceinline__ uint32_t f2tf(float x) {
    uint32_t r;
    asm("cvt.rna.tf32.f32 %0, %1;" : "=r"(r) : "f"(x));
    return r;
}
__device__ __forceinline__ void mma_tf32(float* c, const uint32_t* a,
                                         uint32_t b0, uint32_t b1) {
    asm("mma.sync.aligned.m16n8k8.row.col.f32.tf32.tf32.f32 "
        "{%0,%1,%2,%3},{%4,%5,%6,%7},{%8,%9},{%0,%1,%2,%3};"
        : "+f"(c[0]), "+f"(c[1]), "+f"(c[2]), "+f"(c[3])
        : "r"(a[0]), "r"(a[1]), "r"(a[2]), "r"(a[3]), "r"(b0), "r"(b1));
}
__device__ __forceinline__ void cp16(uint32_t dst, const void* src, int sz) {
    asm volatile("cp.async.ca.shared.global [%0], [%1], 16, %2;"
                 :: "r"(dst), "l"(src), "r"(sz));
}
__device__ __forceinline__ void cp_commit() { asm volatile("cp.async.commit_group;"); }
__device__ __forceinline__ void cp_wait1()  { asm volatile("cp.async.wait_group 1;"); }
__device__ __forceinline__ void cp_wait0()  { asm volatile("cp.async.wait_group 0;"); }

#define APITCH 20
#define BPITCH 136
#define SM_A_BYTES (2 * 128 * APITCH * 4)
#define SM_B_BYTES (2 * 16 * BPITCH * 4)
#define SM_GEMM_BYTES (SM_A_BYTES + SM_B_BYTES)

// grid partition constants
#define GA 391           // author gemm blocks
#define GP 391           // paper gemm blocks
#define GH 1024          // histogram blocks
#define GS 2048          // scatter blocks
#define GAL 1563         // alpha1 blocks
#define GPL 1563         // alpha3 blocks
#define GSEM 782         // semantic blocks (391 x 2)
#define GST 98           // stats blocks (512 rows each)

// ---------------- init ----------------
__global__ void init_kernel() {
    int idx = blockIdx.x * blockDim.x + threadIdx.x;
    int stride = gridDim.x * blockDim.x;
    for (int i = idx; i < 2 * NP; i += stride) g_cnt[i] = 0;
    if (idx < CC) {
        g_Sa[idx] = 0.f; g_Sb[idx] = 0.f;
        g_Saa[idx] = 0.f; g_Sbb[idx] = 0.f; g_Sab[idx] = 0.f;
    }
    if (idx < 2) g_wsum[idx] = 0.f;
}

// ---------------- gemm body (tf32 mma, double-buffered) ----------------
template <int KDIM>
__device__ __forceinline__ void gemm_body(
        const float* __restrict__ X, const float* __restrict__ W,
        const float* __restrict__ bias, float* __restrict__ out,
        int Nrows, int bx, char* smraw) {
    float* As = (float*)smraw;                       // [2][128*APITCH]
    float* Bs = (float*)(smraw + SM_A_BYTES);        // [2][16*BPITCH]
    int tid = threadIdx.x, w = tid >> 5, lane = tid & 31;
    int row0 = bx * 128;

    int arow = tid >> 1, ak = (tid & 1) * 8;
    int brow = tid >> 4, bc = (tid & 15) * 8;
    int garow = row0 + arow;
    int aok = (garow < Nrows) ? 16 : 0;
    const float* abase = X + (size_t)(aok ? garow : 0) * KDIM + ak;
    const float* bbase = W + (size_t)brow * CC + bc;

    uint32_t dA0 = (uint32_t)__cvta_generic_to_shared(&As[arow * APITCH + ak]);
    uint32_t dA1 = dA0 + SM_A_BYTES / 2;
    uint32_t dB0 = (uint32_t)__cvta_generic_to_shared(&Bs[brow * BPITCH + bc]);
    uint32_t dB1 = dB0 + SM_B_BYTES / 2;

    const int NT = KDIM / 16;
    cp16(dA0, abase, aok); cp16(dA0 + 16, abase + 4, aok);
    cp16(dB0, bbase, 16);  cp16(dB0 + 16, bbase + 4, 16);
    cp_commit();

    float acc[16][4];
#pragma unroll
    for (int nt = 0; nt < 16; nt++)
#pragma unroll
        for (int j = 0; j < 4; j++) acc[nt][j] = 0.f;

    int g = lane >> 2, t4 = lane & 3;

    for (int kt = 0; kt < NT; kt++) {
        if (kt + 1 < NT) {
            uint32_t dA = ((kt + 1) & 1) ? dA1 : dA0;
            uint32_t dB = ((kt + 1) & 1) ? dB1 : dB0;
            const float* ap = abase + (kt + 1) * 16;
            const float* bp = bbase + (size_t)(kt + 1) * 16 * CC;
            cp16(dA, ap, aok); cp16(dA + 16, ap + 4, aok);
            cp16(dB, bp, 16);  cp16(dB + 16, bp + 4, 16);
            cp_commit();
            cp_wait1();
        } else {
            cp_wait0();
        }
        __syncthreads();

        const float* Ab = As + (kt & 1) * (128 * APITCH);
        const float* Bb = Bs + (kt & 1) * (16 * BPITCH);

        uint32_t afr[2][4];
#pragma unroll
        for (int s = 0; s < 2; s++) {
            int k = s * 8 + t4;
            afr[s][0] = f2tf(Ab[(w * 16 + g) * APITCH + k]);
            afr[s][1] = f2tf(Ab[(w * 16 + g + 8) * APITCH + k]);
            afr[s][2] = f2tf(Ab[(w * 16 + g) * APITCH + k + 4]);
            afr[s][3] = f2tf(Ab[(w * 16 + g + 8) * APITCH + k + 4]);
        }
#pragma unroll
        for (int nt = 0; nt < 16; nt++) {
            int col = nt * 8 + g;
#pragma unroll
            for (int s = 0; s < 2; s++) {
                int kr = s * 8 + t4;
                uint32_t b0 = f2tf(Bb[kr * BPITCH + col]);
                uint32_t b1 = f2tf(Bb[(kr + 4) * BPITCH + col]);
                mma_tf32(acc[nt], afr[s], b0, b1);
            }
        }
        __syncthreads();
    }

    int t2 = t4 * 2;
    int r1 = row0 + w * 16 + g;
    int r2 = r1 + 8;
#pragma unroll
    for (int nt = 0; nt < 16; nt++) {
        int col = nt * 8 + t2;
        float2 bb = *(const float2*)(bias + col);
        if (r1 < Nrows) {
            float2 v = make_float2(acc[nt][0] + bb.x, acc[nt][1] + bb.y);
            *(float2*)(out + (size_t)r1 * CC + col) = v;
        }
        if (r2 < Nrows) {
            float2 v = make_float2(acc[nt][2] + bb.x, acc[nt][3] + bb.y);
            *(float2*)(out + (size_t)r2 * CC + col) = v;
        }
    }
}

__device__ __forceinline__ void hist_body(const int* __restrict__ e_ap,
                                          const int* __restrict__ e_pp, int bx) {
    for (int idx = bx * 256 + threadIdx.x; idx < 2 * EE; idx += GH * 256) {
        int t = (idx >= EE);
        int e = idx - t * EE;
        const int* ed = t ? e_pp : e_ap;
        int dst = ed[EE + e];
        atomicAdd(&g_cnt[t * NP + dst], 1);
    }
}

// ---------------- phase1: gemm_a | gemm_p | hist ----------------
__global__ __launch_bounds__(256) void phase1_kernel(
        const float* __restrict__ xa, const float* __restrict__ Wa, const float* __restrict__ ba,
        const float* __restrict__ xp, const float* __restrict__ Wp, const float* __restrict__ bp,
        const int* __restrict__ e_ap, const int* __restrict__ e_pp) {
    __shared__ __align__(16) char sm[SM_GEMM_BYTES];
    float* p_h_a = g_h_a;
    float* p_h_p = g_h_p;
    int bx = blockIdx.x;
    if (bx < GA) {
        gemm_body<FA>(xa, Wa, ba, p_h_a, NA, bx, sm);
    } else if (bx < GA + GP) {
        gemm_body<FP>(xp, Wp, bp, p_h_p, NP, bx - GA, sm);
    } else {
        hist_body(e_ap, e_pp, bx - GA - GP);
    }
}

// ---------------- scan ----------------
#define SCAN_T 1024
#define SCAN_CHUNK 49
__global__ void scan_kernel() {
    int t = blockIdx.x;
    int tid = threadIdx.x;
    const int* cnt = g_cnt + t * NP;
    int* rowptr = g_rowptr + t * (NP + 1);
    int* cur = g_cur + t * NP;

    int lo = tid * SCAN_CHUNK;
    int hi = lo + SCAN_CHUNK; if (hi > NP) hi = NP;
    int tsum = 0;
    for (int i = lo; i < hi; i++) tsum += cnt[i];

    __shared__ int sh[SCAN_T];
    sh[tid] = tsum;
    __syncthreads();
    for (int off = 1; off < SCAN_T; off <<= 1) {
        int v = (tid >= off) ? sh[tid - off] : 0;
        __syncthreads();
        sh[tid] += v;
        __syncthreads();
    }
    int running = sh[tid] - tsum;
    for (int i = lo; i < hi; i++) {
        rowptr[i] = running;
        cur[i] = running;
        running += cnt[i];
    }
    if (tid == 0) rowptr[NP] = EE;
}

// ---------------- phase3 bodies ----------------
__device__ __forceinline__ void scatter_body(const int* __restrict__ e_ap,
                                             const int* __restrict__ e_pp, int bx) {
    for (int idx = bx * 256 + threadIdx.x; idx < 2 * EE; idx += GS * 256) {
        int t = (idx >= EE);
        int e = idx - t * EE;
        const int* ed = t ? e_pp : e_ap;
        int src = ed[e];
        int dst = ed[EE + e];
        int pos = atomicAdd(&g_cur[t * NP + dst], 1);
        g_srcs[(size_t)t * EE + pos] = src;
    }
}

__device__ __forceinline__ void alpha1_body(const float* __restrict__ Hm,
                                            const float* __restrict__ att,
                                            float* __restrict__ out, int N, int bx) {
    __shared__ float a[CC];
    if (threadIdx.x < CC) a[threadIdx.x] = att[threadIdx.x];
    __syncthreads();
    int idx = bx * 256 + threadIdx.x;
    if (idx >= N * HH) return;
    int h = idx & 7, n = idx >> 3;
    const float4* hp = (const float4*)(Hm + (size_t)n * CC + h * DD);
    const float4* ap = (const float4*)(a + h * DD);
    float s = 0.f;
#pragma unroll
    for (int j = 0; j < 4; j++) {
        float4 x = hp[j], w = ap[j];
        s += x.x * w.x + x.y * w.y + x.z * w.z + x.w * w.w;
    }
    out[idx] = s;
}

__device__ __forceinline__ void alpha3_body(const float* __restrict__ Hm,
                                            const float* __restrict__ a1,
                                            const float* __restrict__ a2,
                                            const float* __restrict__ a3,
                                            float* __restrict__ o1, float* __restrict__ o2,
                                            float* __restrict__ o3, int N, int bx) {
    __shared__ float s1[CC], s2[CC], s3[CC];
    if (threadIdx.x < CC) {
        s1[threadIdx.x] = a1[threadIdx.x];
        s2[threadIdx.x] = a2[threadIdx.x];
        s3[threadIdx.x] = a3[threadIdx.x];
    }
    __syncthreads();
    int idx = bx * 256 + threadIdx.x;
    if (idx >= N * HH) return;
    int h = idx & 7, n = idx >> 3;
    const float4* hp = (const float4*)(Hm + (size_t)n * CC + h * DD);
    const float4* p1 = (const float4*)(s1 + h * DD);
    const float4* p2 = (const float4*)(s2 + h * DD);
    const float4* p3 = (const float4*)(s3 + h * DD);
    float r1 = 0.f, r2 = 0.f, r3 = 0.f;
#pragma unroll
    for (int j = 0; j < 4; j++) {
        float4 x = hp[j];
        float4 w1 = p1[j], w2 = p2[j], w3 = p3[j];
        r1 += x.x * w1.x + x.y * w1.y + x.z * w1.z + x.w * w1.w;
        r2 += x.x * w2.x + x.y * w2.y + x.z * w2.z + x.w * w2.w;
        r3 += x.x * w3.x + x.y * w3.y + x.z * w3.z + x.w * w3.w;
    }
    o1[idx] = r1; o2[idx] = r2; o3[idx] = r3;
}

// ---------------- phase3: scatter | alpha1 | alpha3 ----------------
__global__ __launch_bounds__(256) void phase3_kernel(
        const int* __restrict__ e_ap, const int* __restrict__ e_pp,
        const float* __restrict__ att_src_ap, const float* __restrict__ att_dst_ap,
        const float* __restrict__ att_src_pp, const float* __restrict__ att_dst_pp) {
    int bx = blockIdx.x;
    if (bx < GS) {
        scatter_body(e_ap, e_pp, bx);
    } else if (bx < GS + GAL) {
        alpha1_body(g_h_a, att_src_ap, g_as_ap, NA, bx - GS);
    } else {
        int b2 = bx - GS - GAL;
        // paper alphas: dst_ap, src_pp, dst_pp all from h_p
        alpha3_body(g_h_p, att_dst_ap, att_src_pp, att_dst_pp,
                    g_ad_ap, g_as_pp, g_ad_pp, NP, b2);
    }
}

// ---------------- merged edge kernel (both types; warp per dst) ----------------
__global__ __launch_bounds__(256) void edge_kernel() {
    __shared__ int   sh_s[8][32];
    __shared__ float sh_e[8][32][8];
    int warp = threadIdx.x >> 5;
    int lane = threadIdx.x & 31;
    int gw = blockIdx.x * 8 + warp;
    if (gw >= 2 * NP) return;
    int t = (gw >= NP);
    int dst = gw - t * NP;

    const int* rowptr = g_rowptr + t * (NP + 1);
    const int* srcs = g_srcs + (size_t)t * EE;
    const float* as = t ? g_as_pp : g_as_ap;
    const float* ad = t ? g_ad_pp : g_ad_ap;
    const float* Hsrc = t ? g_h_p : g_h_a;
    float* outp = g_out01 + (size_t)t * NP * CC;

    int base = rowptr[dst];
    int deg = rowptr[dst + 1] - base;

    float* ow = outp + (size_t)dst * CC;
    if (deg == 0) {
        *(float4*)(ow + lane * 4) = make_float4(0.f, 0.f, 0.f, 0.f);
        return;
    }

    float4 ad0 = *(const float4*)(ad + dst * HH);
    float4 ad1 = *(const float4*)(ad + dst * HH + 4);
    float advs[8] = {ad0.x, ad0.y, ad0.z, ad0.w, ad1.x, ad1.y, ad1.z, ad1.w};

    int myh = lane >> 2;
    float4 acc = make_float4(0.f, 0.f, 0.f, 0.f);
    float denom = 0.f;

    for (int chunk = 0; chunk < deg; chunk += 32) {
        int n = min(32, deg - chunk);
        if (lane < n) {
            int s = srcs[base + chunk + lane];
            sh_s[warp][lane] = s;
            float4 a0 = *(const float4*)(as + s * HH);
            float4 a1 = *(const float4*)(as + s * HH + 4);
            float al[8] = {a0.x, a0.y, a0.z, a0.w, a1.x, a1.y, a1.z, a1.w};
            float e[8];
#pragma unroll
            for (int h = 0; h < 8; h++) {
                float v = al[h] + advs[h];
                v = (v >= 0.f) ? v : 0.2f * v;
                e[h] = __expf(v);
            }
            *(float4*)&sh_e[warp][lane][0] = make_float4(e[0], e[1], e[2], e[3]);
            *(float4*)&sh_e[warp][lane][4] = make_float4(e[4], e[5], e[6], e[7]);
        }
        __syncwarp();
#pragma unroll 4
        for (int i = 0; i < n; i++) {
            int s = sh_s[warp][i];
            float wgt = sh_e[warp][i][myh];
            float4 hv = *(const float4*)(Hsrc + (size_t)s * CC + lane * 4);
            denom += wgt;
            acc.x += wgt * hv.x; acc.y += wgt * hv.y;
            acc.z += wgt * hv.z; acc.w += wgt * hv.w;
        }
        __syncwarp();
    }
    float inv = 1.f / denom;
    float4 v = make_float4(fmaxf(acc.x * inv, 0.f), fmaxf(acc.y * inv, 0.f),
                           fmaxf(acc.z * inv, 0.f), fmaxf(acc.w * inv, 0.f));
    *(float4*)(ow + lane * 4) = v;
}

// ---------------- phase5 bodies ----------------
__device__ __forceinline__ void semantic_body(
        const float* __restrict__ kW, const float* __restrict__ kb,
        const float* __restrict__ q, int rsel, int bx, char* smraw) {
    const float* X = g_out01 + (size_t)rsel * NP * CC;
    float* As = (float*)smraw;
    float* Bs = (float*)(smraw + SM_A_BYTES);
    float* red = (float*)(smraw + SM_GEMM_BYTES);
    int tid = threadIdx.x, w = tid >> 5, lane = tid & 31;
    int row0 = bx * 128;

    int arow = tid >> 1, ak = (tid & 1) * 8;
    int brow = tid >> 4, bc = (tid & 15) * 8;
    int garow = row0 + arow;
    int aok = (garow < NP) ? 16 : 0;
    const float* abase = X + (size_t)(aok ? garow : 0) * CC + ak;
    const float* bbase = kW + (size_t)brow * CC + bc;

    uint32_t dA0 = (uint32_t)__cvta_generic_to_shared(&As[arow * APITCH + ak]);
    uint32_t dA1 = dA0 + SM_A_BYTES / 2;
    uint32_t dB0 = (uint32_t)__cvta_generic_to_shared(&Bs[brow * BPITCH + bc]);
    uint32_t dB1 = dB0 + SM_B_BYTES / 2;

    const int NT = CC / 16;
    cp16(dA0, abase, aok); cp16(dA0 + 16, abase + 4, aok);
    cp16(dB0, bbase, 16);  cp16(dB0 + 16, bbase + 4, 16);
    cp_commit();

    float acc[16][4];
#pragma unroll
    for (int nt = 0; nt < 16; nt++)
#pragma unroll
        for (int j = 0; j < 4; j++) acc[nt][j] = 0.f;

    int g = lane >> 2, t4 = lane & 3;

    for (int kt = 0; kt < NT; kt++) {
        if (kt + 1 < NT) {
            uint32_t dA = ((kt + 1) & 1) ? dA1 : dA0;
            uint32_t dB = ((kt + 1) & 1) ? dB1 : dB0;
            const float* ap = abase + (kt + 1) * 16;
            const float* bp = bbase + (size_t)(kt + 1) * 16 * CC;
            cp16(dA, ap, aok); cp16(dA + 16, ap + 4, aok);
            cp16(dB, bp, 16);  cp16(dB + 16, bp + 4, 16);
            cp_commit();
            cp_wait1();
        } else {
            cp_wait0();
        }
        __syncthreads();

        const float* Ab = As + (kt & 1) * (128 * APITCH);
        const float* Bb = Bs + (kt & 1) * (16 * BPITCH);

        uint32_t afr[2][4];
#pragma unroll
        for (int s = 0; s < 2; s++) {
            int k = s * 8 + t4;
            afr[s][0] = f2tf(Ab[(w * 16 + g) * APITCH + k]);
            afr[s][1] = f2tf(Ab[(w * 16 + g + 8) * APITCH + k]);
            afr[s][2] = f2tf(Ab[(w * 16 + g) * APITCH + k + 4]);
            afr[s][3] = f2tf(Ab[(w * 16 + g + 8) * APITCH + k + 4]);
        }
#pragma unroll
        for (int nt = 0; nt < 16; nt++) {
            int col = nt * 8 + g;
#pragma unroll
            for (int s = 0; s < 2; s++) {
                int kr = s * 8 + t4;
                uint32_t b0 = f2tf(Bb[kr * BPITCH + col]);
                uint32_t b1 = f2tf(Bb[(kr + 4) * BPITCH + col]);
                mma_tf32(acc[nt], afr[s], b0, b1);
            }
        }
        __syncthreads();
    }

    int t2 = t4 * 2;
    int r1 = row0 + w * 16 + g;
    int r2 = r1 + 8;
    float part = 0.f;
#pragma unroll
    for (int nt = 0; nt < 16; nt++) {
        int col = nt * 8 + t2;
        float2 kb2 = *(const float2*)(kb + col);
        float2 q2 = *(const float2*)(q + col);
        if (r1 < NP)
            part += tanh_fast(acc[nt][0] + kb2.x) * q2.x
                  + tanh_fast(acc[nt][1] + kb2.y) * q2.y;
        if (r2 < NP)
            part += tanh_fast(acc[nt][2] + kb2.x) * q2.x
                  + tanh_fast(acc[nt][3] + kb2.y) * q2.y;
    }
#pragma unroll
    for (int o = 16; o; o >>= 1) part += __shfl_xor_sync(0xFFFFFFFFu, part, o);
    if (lane == 0) red[w] = part;
    __syncthreads();
    if (tid == 0) {
        float s = 0.f;
#pragma unroll
        for (int i = 0; i < 8; i++) s += red[i];
        atomicAdd(&g_wsum[rsel], s);
    }
}

#define STAT_ROWS 512
__device__ __forceinline__ void stats5_body(int bx) {
    int tid = threadIdx.x;
    int c = tid & 127;
    int half = tid >> 7;   // 0 or 1
    const float* o0 = g_out01;
    const float* o1 = g_out01 + (size_t)NP * CC;
    int r0 = bx * STAT_ROWS + half;
    int r1 = bx * STAT_ROWS + STAT_ROWS; if (r1 > NP) r1 = NP;
    float sa = 0.f, sb = 0.f, saa = 0.f, sbb = 0.f, sab = 0.f;
    for (int r = r0; r < r1; r += 2) {
        float a = o0[(size_t)r * CC + c];
        float b = o1[(size_t)r * CC + c];
        sa += a; sb += b;
        saa += a * a; sbb += b * b; sab += a * b;
    }
    atomicAdd(&g_Sa[c], sa);
    atomicAdd(&g_Sb[c], sb);
    atomicAdd(&g_Saa[c], saa);
    atomicAdd(&g_Sbb[c], sbb);
    atomicAdd(&g_Sab[c], sab);
}

// ---------------- phase5: semantic (r=0 | r=1) | stats ----------------
__global__ __launch_bounds__(256) void phase5_kernel(
        const float* __restrict__ kW, const float* __restrict__ kb,
        const float* __restrict__ q) {
    __shared__ __align__(16) char sm[SM_GEMM_BYTES + 32];
    int bx = blockIdx.x;
    if (bx < GSEM) {
        int rsel = (bx >= GSEM / 2);
        semantic_body(kW, kb, q, rsel, bx - rsel * (GSEM / 2), sm);
    } else {
        stats5_body(bx - GSEM);
    }
}

// ---------------- beta + norm params ----------------
__global__ void betanorm_kernel(const float* __restrict__ norm_w,
                                const float* __restrict__ norm_b,
                                const float* __restrict__ norm_ms) {
    int c = threadIdx.x;   // 0..127
    float w0 = g_wsum[0] / (float)NP;
    float w1 = g_wsum[1] / (float)NP;
    float m = fmaxf(w0, w1);
    float e0 = expf(w0 - m), e1 = expf(w1 - m);
    float ssum = e0 + e1;
    float b0 = e0 / ssum, b1 = e1 / ssum;
    if (c == 0) { g_beta[0] = b0; g_beta[1] = b1; }

    float mean = (b0 * g_Sa[c] + b1 * g_Sb[c]) / (float)NP;
    float eo2 = (b0 * b0 * g_Saa[c] + 2.f * b0 * b1 * g_Sab[c]
                 + b1 * b1 * g_Sbb[c]) / (float)NP;
    float mm = mean * norm_ms[c];
    float var = eo2 - 2.f * mm * mean + mm * mm;
    float A = norm_w[c] * rsqrtf(var + EPSV);
    g_nA[c] = A;
    g_nB[c] = norm_b[c] - mm * A;
}

// ---------------- fused normalize + classifier ----------------
__global__ void final_kernel(const float* __restrict__ linW,
                             const float* __restrict__ linb,
                             float* __restrict__ y) {
    __shared__ float rowbuf[16][CC];
    __shared__ float lw[CC * OUTC];
    __shared__ float lb[OUTC];
    int tid = threadIdx.x;
    for (int i = tid; i < CC * OUTC; i += 256) lw[i] = linW[i];
    if (tid < OUTC) lb[tid] = linb[tid];
    float b0 = g_beta[0], b1 = g_beta[1];
    const float* o0 = g_out01;
    const float* o1 = g_out01 + (size_t)NP * CC;
    int nrow0 = blockIdx.x * 16;
#pragma unroll
    for (int j = 0; j < 8; j++) {
        int i = tid + j * 256;
        int r = i >> 7, c = i & 127;
        int gr = nrow0 + r;
        float v = 0.f;
        if (gr < NP) {
            v = b0 * o0[(size_t)gr * CC + c] + b1 * o1[(size_t)gr * CC + c];
            v = v * g_nA[c] + g_nB[c];
        }
        rowbuf[r][c] = v;
    }
    __syncthreads();
    int r = tid >> 4, o = tid & 15;
    int gr = nrow0 + r;
    if (gr < NP) {
        float s = lb[o];
#pragma unroll
        for (int c = 0; c < CC; c++) s += rowbuf[r][c] * lw[c * OUTC + o];
        y[(size_t)gr * OUTC + o] = s;
    }
}

// ---------------- launch ----------------
extern "C" void kernel_launch(void* const* d_in, const int* in_sizes, int n_in,
                              void* d_out, int out_size) {
    const float* x_author = (const float*)d_in[0];
    const float* x_paper  = (const float*)d_in[1];
    const float* W_a      = (const float*)d_in[2];
    const float* b_a      = (const float*)d_in[3];
    const float* W_p      = (const float*)d_in[4];
    const float* b_p      = (const float*)d_in[5];
    const float* att_src_ap = (const float*)d_in[6];
    const float* att_dst_ap = (const float*)d_in[7];
    const float* att_src_pp = (const float*)d_in[8];
    const float* att_dst_pp = (const float*)d_in[9];
    const float* k_W      = (const float*)d_in[10];
    const float* k_b      = (const float*)d_in[11];
    const float* q        = (const float*)d_in[12];
    const float* norm_w   = (const float*)d_in[13];
    const float* norm_b   = (const float*)d_in[14];
    const float* norm_ms  = (const float*)d_in[15];
    const float* lin_W    = (const float*)d_in[16];
    const float* lin_b    = (const float*)d_in[17];
    const int*   edge_ap  = (const int*)d_in[18];
    const int*   edge_pp  = (const int*)d_in[19];
    float* y = (float*)d_out;

    // 0. init
    init_kernel<<<128, 256>>>();

    // 1. gemm_a | gemm_p | hist  (independent, merged)
    phase1_kernel<<<GA + GP + GH, 256>>>(x_author, W_a, b_a,
                                         x_paper, W_p, b_p,
                                         edge_ap, edge_pp);

    // 2. prefix scan (needs hist)
    scan_kernel<<<2, SCAN_T>>>();

    // 3. scatter | alpha1 | alpha3  (need scan / gemms)
    phase3_kernel<<<GS + GAL + GPL, 256>>>(edge_ap, edge_pp,
                                           att_src_ap, att_dst_ap,
                                           att_src_pp, att_dst_pp);

    // 4. fused edge softmax + aggregation, both types
    edge_kernel<<<(2 * NP + 7) / 8, 256>>>();

    // 5. semantic gemms | beta-independent stats
    phase5_kernel<<<GSEM + GST, 256>>>(k_W, k_b, q);

    // 6. beta + norm params
    betanorm_kernel<<<1, CC>>>(norm_w, norm_b, norm_ms);

    // 7. normalize + classify
    final_kernel<<<(NP + 15) / 16, 256>>>(lin_W, lin_b, y);
}

// round 7
// speedup vs baseline: 1.8624x; 1.1153x over previous
#include <cuda_runtime.h>
#include <math.h>
#include <stdint.h>

#define NA 50000
#define NP 50000
#define EE 600000
#define HH 8
#define DD 16
#define CC 128
#define OUTC 16
#define FA 256
#define FP 128
#define EPSV 1e-5f

// ---------------- device scratch ----------------
__device__ float    g_h_a[(size_t)NA * CC];
__device__ float    g_h_p[(size_t)NP * CC];
__device__ float    g_as_ap[NA * HH];
__device__ float    g_ad_ap[NP * HH];
__device__ float    g_as_pp[NP * HH];
__device__ float    g_ad_pp[NP * HH];
__device__ int      g_cnt[2 * NP];
__device__ int      g_rank[2 * (size_t)EE];
__device__ int      g_rowptr[2 * (NP + 1)];
__device__ int      g_srcs[2 * (size_t)EE];
__device__ float    g_out01[2 * (size_t)NP * CC]; // relu-applied
__device__ float    g_Wat[FA * CC];               // permuted tf32 weights
__device__ float    g_Wpt[FP * CC];
__device__ float    g_kWt[CC * CC];
__device__ float    g_wsum[2];
__device__ float    g_beta[2];
__device__ float    g_Sa[CC], g_Sb[CC], g_Saa[CC], g_Sbb[CC], g_Sab[CC];
__device__ float    g_nA[CC];
__device__ float    g_nB[CC];

// ---------------- helpers ----------------
__device__ __forceinline__ float tanh_fast(float x) {
    float y;
    asm("tanh.approx.f32 %0, %1;" : "=f"(y) : "f"(x));
    return y;
}
__device__ __forceinline__ uint32_t f2tf(float x) {
    uint32_t r;
    asm("cvt.rna.tf32.f32 %0, %1;" : "=r"(r) : "f"(x));
    return r;
}
__device__ __forceinline__ void mma_tf32(float* c, const uint32_t* a,
                                         uint32_t b0, uint32_t b1) {
    asm("mma.sync.aligned.m16n8k8.row.col.f32.tf32.tf32.f32 "
        "{%0,%1,%2,%3},{%4,%5,%6,%7},{%8,%9},{%0,%1,%2,%3};"
        : "+f"(c[0]), "+f"(c[1]), "+f"(c[2]), "+f"(c[3])
        : "r"(a[0]), "r"(a[1]), "r"(a[2]), "r"(a[3]), "r"(b0), "r"(b1));
}
__device__ __forceinline__ void cp16(uint32_t dst, const void* src, int sz) {
    asm volatile("cp.async.ca.shared.global [%0], [%1], 16, %2;"
                 :: "r"(dst), "l"(src), "r"(sz));
}
__device__ __forceinline__ void cp_commit() { asm volatile("cp.async.commit_group;"); }
__device__ __forceinline__ void cp_wait1()  { asm volatile("cp.async.wait_group 1;"); }
__device__ __forceinline__ void cp_wait0()  { asm volatile("cp.async.wait_group 0;"); }

#define APITCH 20
#define SM_A_BYTES (2 * 128 * APITCH * 4)
#define SM_B_BYTES (2 * 2048 * 4)              // permuted B: 2048 floats/stage
#define SM_GEMM_BYTES (SM_A_BYTES + SM_B_BYTES)

// grid partition constants
#define GA 391
#define GP 391
#define GH 1024
#define GS 2048
#define GAL 1563
#define GPL 1563
#define GSEM 782
#define GST 98

// ---------------- init: zero accumulators + build permuted tf32 weights ----------------
__device__ __forceinline__ void build_wt(const float* __restrict__ W,
                                         float* __restrict__ Wt,
                                         int total, int idx, int stride) {
    for (int o = idx; o < total; o += stride) {
        int kt = o >> 11;            // / 2048
        int rem = o & 2047;
        int col = rem >> 4;
        int u = rem & 15;
        int t4 = u >> 2;
        int j = u & 3;
        int srck = kt * 16 + t4 + 4 * j;
        float v = W[srck * CC + col];
        Wt[o] = __uint_as_float(f2tf(v));
    }
}

__global__ void init_kernel(const float* __restrict__ Wa,
                            const float* __restrict__ Wp,
                            const float* __restrict__ kW) {
    int idx = blockIdx.x * blockDim.x + threadIdx.x;
    int stride = gridDim.x * blockDim.x;
    for (int i = idx; i < 2 * NP; i += stride) g_cnt[i] = 0;
    build_wt(Wa, g_Wat, FA * CC, idx, stride);
    build_wt(Wp, g_Wpt, FP * CC, idx, stride);
    build_wt(kW, g_kWt, CC * CC, idx, stride);
    if (idx < CC) {
        g_Sa[idx] = 0.f; g_Sb[idx] = 0.f;
        g_Saa[idx] = 0.f; g_Sbb[idx] = 0.f; g_Sab[idx] = 0.f;
    }
    if (idx < 2) g_wsum[idx] = 0.f;
}

// ---------------- gemm body (tf32 mma, permuted-B, double-buffered) ----------------
template <int KDIM>
__device__ __forceinline__ void gemm_body(
        const float* __restrict__ X, const float* __restrict__ Wt,
        const float* __restrict__ bias, float* __restrict__ out,
        int Nrows, int bx, char* smraw) {
    float* As = (float*)smraw;                       // [2][128*APITCH]
    float* Bs = (float*)(smraw + SM_A_BYTES);        // [2][2048]
    int tid = threadIdx.x, w = tid >> 5, lane = tid & 31;
    int row0 = bx * 128;

    int arow = tid >> 1, ak = (tid & 1) * 8;
    int garow = row0 + arow;
    int aok = (garow < Nrows) ? 16 : 0;
    const float* abase = X + (size_t)(aok ? garow : 0) * KDIM + ak;
    const float* bbase = Wt + tid * 8;

    uint32_t dA0 = (uint32_t)__cvta_generic_to_shared(&As[arow * APITCH + ak]);
    uint32_t dA1 = dA0 + SM_A_BYTES / 2;
    uint32_t dB0 = (uint32_t)__cvta_generic_to_shared(&Bs[tid * 8]);
    uint32_t dB1 = dB0 + SM_B_BYTES / 2;

    const int NT = KDIM / 16;
    cp16(dA0, abase, aok); cp16(dA0 + 16, abase + 4, aok);
    cp16(dB0, bbase, 16);  cp16(dB0 + 16, bbase + 4, 16);
    cp_commit();

    float acc[16][4];
#pragma unroll
    for (int nt = 0; nt < 16; nt++)
#pragma unroll
        for (int j = 0; j < 4; j++) acc[nt][j] = 0.f;

    int g = lane >> 2, t4 = lane & 3;

    for (int kt = 0; kt < NT; kt++) {
        if (kt + 1 < NT) {
            uint32_t dA = ((kt + 1) & 1) ? dA1 : dA0;
            uint32_t dB = ((kt + 1) & 1) ? dB1 : dB0;
            const float* ap = abase + (kt + 1) * 16;
            const float* bp = bbase + (size_t)(kt + 1) * 2048;
            cp16(dA, ap, aok); cp16(dA + 16, ap + 4, aok);
            cp16(dB, bp, 16);  cp16(dB + 16, bp + 4, 16);
            cp_commit();
            cp_wait1();
        } else {
            cp_wait0();
        }
        __syncthreads();

        const float* Ab = As + (kt & 1) * (128 * APITCH);
        const uint32_t* Bb = (const uint32_t*)(Bs + (kt & 1) * 2048);

        uint32_t afr[2][4];
#pragma unroll
        for (int s = 0; s < 2; s++) {
            int k = s * 8 + t4;
            afr[s][0] = f2tf(Ab[(w * 16 + g) * APITCH + k]);
            afr[s][1] = f2tf(Ab[(w * 16 + g + 8) * APITCH + k]);
            afr[s][2] = f2tf(Ab[(w * 16 + g) * APITCH + k + 4]);
            afr[s][3] = f2tf(Ab[(w * 16 + g + 8) * APITCH + k + 4]);
        }
#pragma unroll
        for (int nt = 0; nt < 16; nt++) {
            uint4 bq = *(const uint4*)&Bb[(nt * 8 + g) * 16 + t4 * 4];
            mma_tf32(acc[nt], afr[0], bq.x, bq.y);
            mma_tf32(acc[nt], afr[1], bq.z, bq.w);
        }
        __syncthreads();
    }

    int t2 = t4 * 2;
    int r1 = row0 + w * 16 + g;
    int r2 = r1 + 8;
#pragma unroll
    for (int nt = 0; nt < 16; nt++) {
        int col = nt * 8 + t2;
        float2 bb = *(const float2*)(bias + col);
        if (r1 < Nrows) {
            float2 v = make_float2(acc[nt][0] + bb.x, acc[nt][1] + bb.y);
            *(float2*)(out + (size_t)r1 * CC + col) = v;
        }
        if (r2 < Nrows) {
            float2 v = make_float2(acc[nt][2] + bb.x, acc[nt][3] + bb.y);
            *(float2*)(out + (size_t)r2 * CC + col) = v;
        }
    }
}

__device__ __forceinline__ void hist_body(const int* __restrict__ e_ap,
                                          const int* __restrict__ e_pp, int bx) {
    for (int idx = bx * 256 + threadIdx.x; idx < 2 * EE; idx += GH * 256) {
        int t = (idx >= EE);
        int e = idx - t * EE;
        const int* ed = t ? e_pp : e_ap;
        int dst = ed[EE + e];
        int r = atomicAdd(&g_cnt[t * NP + dst], 1);
        g_rank[idx] = r;
    }
}

// ---------------- phase1: gemm_a | gemm_p | hist ----------------
__global__ __launch_bounds__(256) void phase1_kernel(
        const float* __restrict__ xa, const float* __restrict__ ba,
        const float* __restrict__ xp, const float* __restrict__ bp,
        const int* __restrict__ e_ap, const int* __restrict__ e_pp) {
    __shared__ __align__(16) char sm[SM_GEMM_BYTES];
    int bx = blockIdx.x;
    if (bx < GA) {
        gemm_body<FA>(xa, g_Wat, ba, g_h_a, NA, bx, sm);
    } else if (bx < GA + GP) {
        gemm_body<FP>(xp, g_Wpt, bp, g_h_p, NP, bx - GA, sm);
    } else {
        hist_body(e_ap, e_pp, bx - GA - GP);
    }
}

// ---------------- scan ----------------
#define SCAN_T 1024
#define SCAN_CHUNK 49
__global__ void scan_kernel() {
    int t = blockIdx.x;
    int tid = threadIdx.x;
    const int* cnt = g_cnt + t * NP;
    int* rowptr = g_rowptr + t * (NP + 1);

    int lo = tid * SCAN_CHUNK;
    int hi = lo + SCAN_CHUNK; if (hi > NP) hi = NP;
    int tsum = 0;
    for (int i = lo; i < hi; i++) tsum += cnt[i];

    __shared__ int sh[SCAN_T];
    sh[tid] = tsum;
    __syncthreads();
    for (int off = 1; off < SCAN_T; off <<= 1) {
        int v = (tid >= off) ? sh[tid - off] : 0;
        __syncthreads();
        sh[tid] += v;
        __syncthreads();
    }
    int running = sh[tid] - tsum;
    for (int i = lo; i < hi; i++) {
        rowptr[i] = running;
        running += cnt[i];
    }
    if (tid == 0) rowptr[NP] = EE;
}

// ---------------- phase3 bodies ----------------
__device__ __forceinline__ void scatter_body(const int* __restrict__ e_ap,
                                             const int* __restrict__ e_pp, int bx) {
    for (int idx = bx * 256 + threadIdx.x; idx < 2 * EE; idx += GS * 256) {
        int t = (idx >= EE);
        int e = idx - t * EE;
        const int* ed = t ? e_pp : e_ap;
        int src = ed[e];
        int dst = ed[EE + e];
        int pos = g_rowptr[t * (NP + 1) + dst] + g_rank[idx];
        g_srcs[(size_t)t * EE + pos] = src;
    }
}

__device__ __forceinline__ void alpha1_body(const float* __restrict__ Hm,
                                            const float* __restrict__ att,
                                            float* __restrict__ out, int N, int bx) {
    __shared__ float a[CC];
    if (threadIdx.x < CC) a[threadIdx.x] = att[threadIdx.x];
    __syncthreads();
    int idx = bx * 256 + threadIdx.x;
    if (idx >= N * HH) return;
    int h = idx & 7, n = idx >> 3;
    const float4* hp = (const float4*)(Hm + (size_t)n * CC + h * DD);
    const float4* ap = (const float4*)(a + h * DD);
    float s = 0.f;
#pragma unroll
    for (int j = 0; j < 4; j++) {
        float4 x = hp[j], w = ap[j];
        s += x.x * w.x + x.y * w.y + x.z * w.z + x.w * w.w;
    }
    out[idx] = s;
}

__device__ __forceinline__ void alpha3_body(const float* __restrict__ Hm,
                                            const float* __restrict__ a1,
                                            const float* __restrict__ a2,
                                            const float* __restrict__ a3,
                                            float* __restrict__ o1, float* __restrict__ o2,
                                            float* __restrict__ o3, int N, int bx) {
    __shared__ float s1[CC], s2[CC], s3[CC];
    if (threadIdx.x < CC) {
        s1[threadIdx.x] = a1[threadIdx.x];
        s2[threadIdx.x] = a2[threadIdx.x];
        s3[threadIdx.x] = a3[threadIdx.x];
    }
    __syncthreads();
    int idx = bx * 256 + threadIdx.x;
    if (idx >= N * HH) return;
    int h = idx & 7, n = idx >> 3;
    const float4* hp = (const float4*)(Hm + (size_t)n * CC + h * DD);
    const float4* p1 = (const float4*)(s1 + h * DD);
    const float4* p2 = (const float4*)(s2 + h * DD);
    const float4* p3 = (const float4*)(s3 + h * DD);
    float r1 = 0.f, r2 = 0.f, r3 = 0.f;
#pragma unroll
    for (int j = 0; j < 4; j++) {
        float4 x = hp[j];
        float4 w1 = p1[j], w2 = p2[j], w3 = p3[j];
        r1 += x.x * w1.x + x.y * w1.y + x.z * w1.z + x.w * w1.w;
        r2 += x.x * w2.x + x.y * w2.y + x.z * w2.z + x.w * w2.w;
        r3 += x.x * w3.x + x.y * w3.y + x.z * w3.z + x.w * w3.w;
    }
    o1[idx] = r1; o2[idx] = r2; o3[idx] = r3;
}

// ---------------- phase3: scatter | alpha1 | alpha3 ----------------
__global__ __launch_bounds__(256) void phase3_kernel(
        const int* __restrict__ e_ap, const int* __restrict__ e_pp,
        const float* __restrict__ att_src_ap, const float* __restrict__ att_dst_ap,
        const float* __restrict__ att_src_pp, const float* __restrict__ att_dst_pp) {
    int bx = blockIdx.x;
    if (bx < GS) {
        scatter_body(e_ap, e_pp, bx);
    } else if (bx < GS + GAL) {
        alpha1_body(g_h_a, att_src_ap, g_as_ap, NA, bx - GS);
    } else {
        int b2 = bx - GS - GAL;
        alpha3_body(g_h_p, att_dst_ap, att_src_pp, att_dst_pp,
                    g_ad_ap, g_as_pp, g_ad_pp, NP, b2);
    }
}

// ---------------- merged edge kernel (both types; warp per dst) ----------------
__global__ __launch_bounds__(256) void edge_kernel() {
    __shared__ int   sh_s[8][32];
    __shared__ float sh_e[8][32][8];
    int warp = threadIdx.x >> 5;
    int lane = threadIdx.x & 31;
    int gw = blockIdx.x * 8 + warp;
    if (gw >= 2 * NP) return;
    int t = (gw >= NP);
    int dst = gw - t * NP;

    const int* rowptr = g_rowptr + t * (NP + 1);
    const int* srcs = g_srcs + (size_t)t * EE;
    const float* as = t ? g_as_pp : g_as_ap;
    const float* ad = t ? g_ad_pp : g_ad_ap;
    const float* Hsrc = t ? g_h_p : g_h_a;
    float* outp = g_out01 + (size_t)t * NP * CC;

    int base = rowptr[dst];
    int deg = rowptr[dst + 1] - base;

    float* ow = outp + (size_t)dst * CC;
    if (deg == 0) {
        *(float4*)(ow + lane * 4) = make_float4(0.f, 0.f, 0.f, 0.f);
        return;
    }

    float4 ad0 = *(const float4*)(ad + dst * HH);
    float4 ad1 = *(const float4*)(ad + dst * HH + 4);
    float advs[8] = {ad0.x, ad0.y, ad0.z, ad0.w, ad1.x, ad1.y, ad1.z, ad1.w};

    int myh = lane >> 2;
    float4 acc = make_float4(0.f, 0.f, 0.f, 0.f);
    float denom = 0.f;

    for (int chunk = 0; chunk < deg; chunk += 32) {
        int n = min(32, deg - chunk);
        if (lane < n) {
            int s = srcs[base + chunk + lane];
            sh_s[warp][lane] = s;
            float4 a0 = *(const float4*)(as + s * HH);
            float4 a1 = *(const float4*)(as + s * HH + 4);
            float al[8] = {a0.x, a0.y, a0.z, a0.w, a1.x, a1.y, a1.z, a1.w};
            float e[8];
#pragma unroll
            for (int h = 0; h < 8; h++) {
                float v = al[h] + advs[h];
                v = (v >= 0.f) ? v : 0.2f * v;
                e[h] = __expf(v);
            }
            *(float4*)&sh_e[warp][lane][0] = make_float4(e[0], e[1], e[2], e[3]);
            *(float4*)&sh_e[warp][lane][4] = make_float4(e[4], e[5], e[6], e[7]);
        }
        __syncwarp();
#pragma unroll 4
        for (int i = 0; i < n; i++) {
            int s = sh_s[warp][i];
            float wgt = sh_e[warp][i][myh];
            float4 hv = *(const float4*)(Hsrc + (size_t)s * CC + lane * 4);
            denom += wgt;
            acc.x += wgt * hv.x; acc.y += wgt * hv.y;
            acc.z += wgt * hv.z; acc.w += wgt * hv.w;
        }
        __syncwarp();
    }
    float inv = 1.f / denom;
    float4 v = make_float4(fmaxf(acc.x * inv, 0.f), fmaxf(acc.y * inv, 0.f),
                           fmaxf(acc.z * inv, 0.f), fmaxf(acc.w * inv, 0.f));
    *(float4*)(ow + lane * 4) = v;
}

// ---------------- phase5 bodies ----------------
__device__ __forceinline__ void semantic_body(
        const float* __restrict__ kb, const float* __restrict__ q,
        int rsel, int bx, char* smraw) {
    const float* X = g_out01 + (size_t)rsel * NP * CC;
    const float* Wt = g_kWt;
    float* As = (float*)smraw;
    float* Bs = (float*)(smraw + SM_A_BYTES);
    float* red = (float*)(smraw + SM_GEMM_BYTES);
    int tid = threadIdx.x, w = tid >> 5, lane = tid & 31;
    int row0 = bx * 128;

    int arow = tid >> 1, ak = (tid & 1) * 8;
    int garow = row0 + arow;
    int aok = (garow < NP) ? 16 : 0;
    const float* abase = X + (size_t)(aok ? garow : 0) * CC + ak;
    const float* bbase = Wt + tid * 8;

    uint32_t dA0 = (uint32_t)__cvta_generic_to_shared(&As[arow * APITCH + ak]);
    uint32_t dA1 = dA0 + SM_A_BYTES / 2;
    uint32_t dB0 = (uint32_t)__cvta_generic_to_shared(&Bs[tid * 8]);
    uint32_t dB1 = dB0 + SM_B_BYTES / 2;

    const int NT = CC / 16;
    cp16(dA0, abase, aok); cp16(dA0 + 16, abase + 4, aok);
    cp16(dB0, bbase, 16);  cp16(dB0 + 16, bbase + 4, 16);
    cp_commit();

    float acc[16][4];
#pragma unroll
    for (int nt = 0; nt < 16; nt++)
#pragma unroll
        for (int j = 0; j < 4; j++) acc[nt][j] = 0.f;

    int g = lane >> 2, t4 = lane & 3;

    for (int kt = 0; kt < NT; kt++) {
        if (kt + 1 < NT) {
            uint32_t dA = ((kt + 1) & 1) ? dA1 : dA0;
            uint32_t dB = ((kt + 1) & 1) ? dB1 : dB0;
            const float* ap = abase + (kt + 1) * 16;
            const float* bp = bbase + (size_t)(kt + 1) * 2048;
            cp16(dA, ap, aok); cp16(dA + 16, ap + 4, aok);
            cp16(dB, bp, 16);  cp16(dB + 16, bp + 4, 16);
            cp_commit();
            cp_wait1();
        } else {
            cp_wait0();
        }
        __syncthreads();

        const float* Ab = As + (kt & 1) * (128 * APITCH);
        const uint32_t* Bb = (const uint32_t*)(Bs + (kt & 1) * 2048);

        uint32_t afr[2][4];
#pragma unroll
        for (int s = 0; s < 2; s++) {
            int k = s * 8 + t4;
            afr[s][0] = f2tf(Ab[(w * 16 + g) * APITCH + k]);
            afr[s][1] = f2tf(Ab[(w * 16 + g + 8) * APITCH + k]);
            afr[s][2] = f2tf(Ab[(w * 16 + g) * APITCH + k + 4]);
            afr[s][3] = f2tf(Ab[(w * 16 + g + 8) * APITCH + k + 4]);
        }
#pragma unroll
        for (int nt = 0; nt < 16; nt++) {
            uint4 bq = *(const uint4*)&Bb[(nt * 8 + g) * 16 + t4 * 4];
            mma_tf32(acc[nt], afr[0], bq.x, bq.y);
            mma_tf32(acc[nt], afr[1], bq.z, bq.w);
        }
        __syncthreads();
    }

    int t2 = t4 * 2;
    int r1 = row0 + w * 16 + g;
    int r2 = r1 + 8;
    float part = 0.f;
#pragma unroll
    for (int nt = 0; nt < 16; nt++) {
        int col = nt * 8 + t2;
        float2 kb2 = *(const float2*)(kb + col);
        float2 q2 = *(const float2*)(q + col);
        if (r1 < NP)
            part += tanh_fast(acc[nt][0] + kb2.x) * q2.x
                  + tanh_fast(acc[nt][1] + kb2.y) * q2.y;
        if (r2 < NP)
            part += tanh_fast(acc[nt][2] + kb2.x) * q2.x
                  + tanh_fast(acc[nt][3] + kb2.y) * q2.y;
    }
#pragma unroll
    for (int o = 16; o; o >>= 1) part += __shfl_xor_sync(0xFFFFFFFFu, part, o);
    if (lane == 0) red[w] = part;
    __syncthreads();
    if (tid == 0) {
        float s = 0.f;
#pragma unroll
        for (int i = 0; i < 8; i++) s += red[i];
        atomicAdd(&g_wsum[rsel], s);
    }
}

#define STAT_ROWS 512
__device__ __forceinline__ void stats5_body(int bx) {
    int tid = threadIdx.x;
    int c = tid & 127;
    int half = tid >> 7;
    const float* o0 = g_out01;
    const float* o1 = g_out01 + (size_t)NP * CC;
    int r0 = bx * STAT_ROWS + half;
    int r1 = bx * STAT_ROWS + STAT_ROWS; if (r1 > NP) r1 = NP;
    float sa = 0.f, sb = 0.f, saa = 0.f, sbb = 0.f, sab = 0.f;
    for (int r = r0; r < r1; r += 2) {
        float a = o0[(size_t)r * CC + c];
        float b = o1[(size_t)r * CC + c];
        sa += a; sb += b;
        saa += a * a; sbb += b * b; sab += a * b;
    }
    atomicAdd(&g_Sa[c], sa);
    atomicAdd(&g_Sb[c], sb);
    atomicAdd(&g_Saa[c], saa);
    atomicAdd(&g_Sbb[c], sbb);
    atomicAdd(&g_Sab[c], sab);
}

// ---------------- phase5: semantic (r=0 | r=1) | stats ----------------
__global__ __launch_bounds__(256) void phase5_kernel(
        const float* __restrict__ kb, const float* __restrict__ q) {
    __shared__ __align__(16) char sm[SM_GEMM_BYTES + 32];
    int bx = blockIdx.x;
    if (bx < GSEM) {
        int rsel = (bx >= GSEM / 2);
        semantic_body(kb, q, rsel, bx - rsel * (GSEM / 2), sm);
    } else {
        stats5_body(bx - GSEM);
    }
}

// ---------------- beta + norm params ----------------
__global__ void betanorm_kernel(const float* __restrict__ norm_w,
                                const float* __restrict__ norm_b,
                                const float* __restrict__ norm_ms) {
    int c = threadIdx.x;
    float w0 = g_wsum[0] / (float)NP;
    float w1 = g_wsum[1] / (float)NP;
    float m = fmaxf(w0, w1);
    float e0 = expf(w0 - m), e1 = expf(w1 - m);
    float ssum = e0 + e1;
    float b0 = e0 / ssum, b1 = e1 / ssum;
    if (c == 0) { g_beta[0] = b0; g_beta[1] = b1; }

    float mean = (b0 * g_Sa[c] + b1 * g_Sb[c]) / (float)NP;
    float eo2 = (b0 * b0 * g_Saa[c] + 2.f * b0 * b1 * g_Sab[c]
                 + b1 * b1 * g_Sbb[c]) / (float)NP;
    float mm = mean * norm_ms[c];
    float var = eo2 - 2.f * mm * mean + mm * mm;
    float A = norm_w[c] * rsqrtf(var + EPSV);
    g_nA[c] = A;
    g_nB[c] = norm_b[c] - mm * A;
}

// ---------------- fused normalize + classifier ----------------
__global__ void final_kernel(const float* __restrict__ linW,
                             const float* __restrict__ linb,
                             float* __restrict__ y) {
    __shared__ float rowbuf[16][CC];
    __shared__ float lw[CC * OUTC];
    __shared__ float lb[OUTC];
    int tid = threadIdx.x;
    for (int i = tid; i < CC * OUTC; i += 256) lw[i] = linW[i];
    if (tid < OUTC) lb[tid] = linb[tid];
    float b0 = g_beta[0], b1 = g_beta[1];
    const float* o0 = g_out01;
    const float* o1 = g_out01 + (size_t)NP * CC;
    int nrow0 = blockIdx.x * 16;
#pragma unroll
    for (int j = 0; j < 8; j++) {
        int i = tid + j * 256;
        int r = i >> 7, c = i & 127;
        int gr = nrow0 + r;
        float v = 0.f;
        if (gr < NP) {
            v = b0 * o0[(size_t)gr * CC + c] + b1 * o1[(size_t)gr * CC + c];
            v = v * g_nA[c] + g_nB[c];
        }
        rowbuf[r][c] = v;
    }
    __syncthreads();
    int r = tid >> 4, o = tid & 15;
    int gr = nrow0 + r;
    if (gr < NP) {
        float s = lb[o];
#pragma unroll
        for (int c = 0; c < CC; c++) s += rowbuf[r][c] * lw[c * OUTC + o];
        y[(size_t)gr * OUTC + o] = s;
    }
}

// ---------------- launch ----------------
extern "C" void kernel_launch(void* const* d_in, const int* in_sizes, int n_in,
                              void* d_out, int out_size) {
    const float* x_author = (const float*)d_in[0];
    const float* x_paper  = (const float*)d_in[1];
    const float* W_a      = (const float*)d_in[2];
    const float* b_a      = (const float*)d_in[3];
    const float* W_p      = (const float*)d_in[4];
    const float* b_p      = (const float*)d_in[5];
    const float* att_src_ap = (const float*)d_in[6];
    const float* att_dst_ap = (const float*)d_in[7];
    const float* att_src_pp = (const float*)d_in[8];
    const float* att_dst_pp = (const float*)d_in[9];
    const float* k_W      = (const float*)d_in[10];
    const float* k_b      = (const float*)d_in[11];
    const float* q        = (const float*)d_in[12];
    const float* norm_w   = (const float*)d_in[13];
    const float* norm_b   = (const float*)d_in[14];
    const float* norm_ms  = (const float*)d_in[15];
    const float* lin_W    = (const float*)d_in[16];
    const float* lin_b    = (const float*)d_in[17];
    const int*   edge_ap  = (const int*)d_in[18];
    const int*   edge_pp  = (const int*)d_in[19];
    float* y = (float*)d_out;

    // 0. init: zero counters + build permuted tf32 weights
    init_kernel<<<256, 256>>>(W_a, W_p, k_W);

    // 1. gemm_a | gemm_p | hist(+rank)
    phase1_kernel<<<GA + GP + GH, 256>>>(x_author, b_a, x_paper, b_p,
                                         edge_ap, edge_pp);

    // 2. prefix scan
    scan_kernel<<<2, SCAN_T>>>();

    // 3. scatter (atomic-free) | alpha1 | alpha3
    phase3_kernel<<<GS + GAL + GPL, 256>>>(edge_ap, edge_pp,
                                           att_src_ap, att_dst_ap,
                                           att_src_pp, att_dst_pp);

    // 4. fused edge softmax + aggregation, both types
    edge_kernel<<<(2 * NP + 7) / 8, 256>>>();

    // 5. semantic gemms | beta-independent stats
    phase5_kernel<<<GSEM + GST, 256>>>(k_b, q);

    // 6. beta + norm params
    betanorm_kernel<<<1, CC>>>(norm_w, norm_b, norm_ms);

    // 7. normalize + classify
    final_kernel<<<(NP + 15) / 16, 256>>>(lin_W, lin_b, y);
}

// round 8
// speedup vs baseline: 1.9409x; 1.0422x over previous
#include <cuda_runtime.h>
#include <math.h>
#include <stdint.h>

#define NA 50000
#define NP 50000
#define EE 600000
#define HH 8
#define DD 16
#define CC 128
#define OUTC 16
#define FA 256
#define FP 128
#define EPSV 1e-5f

// ---------------- device scratch ----------------
__device__ float    g_h_a[(size_t)NA * CC];
__device__ float    g_h_p[(size_t)NP * CC];
__device__ float    g_as_ap[NA * HH];
__device__ float    g_ad_ap[NP * HH];
__device__ float    g_as_pp[NP * HH];
__device__ float    g_ad_pp[NP * HH];
__device__ int      g_cnt[2 * NP];
__device__ int      g_rank[2 * (size_t)EE];
__device__ int      g_rowptr[2 * (NP + 1)];
__device__ int      g_srcs[2 * (size_t)EE];
__device__ float    g_out01[2 * (size_t)NP * CC]; // relu-applied
__device__ float    g_Wat[FA * CC];               // permuted tf32 weights
__device__ float    g_Wpt[FP * CC];
__device__ float    g_kWt[CC * CC];
__device__ float    g_wsum[2];
__device__ float    g_Sa[CC], g_Sb[CC], g_Saa[CC], g_Sbb[CC], g_Sab[CC];

// ---------------- helpers ----------------
__device__ __forceinline__ float tanh_fast(float x) {
    float y;
    asm("tanh.approx.f32 %0, %1;" : "=f"(y) : "f"(x));
    return y;
}
__device__ __forceinline__ uint32_t f2tf(float x) {
    uint32_t r;
    asm("cvt.rna.tf32.f32 %0, %1;" : "=r"(r) : "f"(x));
    return r;
}
__device__ __forceinline__ void mma_tf32(float* c, const uint32_t* a,
                                         uint32_t b0, uint32_t b1) {
    asm("mma.sync.aligned.m16n8k8.row.col.f32.tf32.tf32.f32 "
        "{%0,%1,%2,%3},{%4,%5,%6,%7},{%8,%9},{%0,%1,%2,%3};"
        : "+f"(c[0]), "+f"(c[1]), "+f"(c[2]), "+f"(c[3])
        : "r"(a[0]), "r"(a[1]), "r"(a[2]), "r"(a[3]), "r"(b0), "r"(b1));
}
__device__ __forceinline__ void cp16(uint32_t dst, const void* src, int sz) {
    asm volatile("cp.async.ca.shared.global [%0], [%1], 16, %2;"
                 :: "r"(dst), "l"(src), "r"(sz));
}
__device__ __forceinline__ void cp_commit() { asm volatile("cp.async.commit_group;"); }
__device__ __forceinline__ void cp_wait1()  { asm volatile("cp.async.wait_group 1;"); }
__device__ __forceinline__ void cp_wait0()  { asm volatile("cp.async.wait_group 0;"); }

#define APITCH 20
#define SM_A_BYTES (2 * 128 * APITCH * 4)
#define SM_B_BYTES (2 * 2048 * 4)
#define SM_GEMM_BYTES (SM_A_BYTES + SM_B_BYTES)

// grid partition constants
#define GA 391
#define GP 391
#define GH 1024
#define GSEM 782
#define GST 98

// ---------------- init: zero counters + build permuted tf32 weights ----------------
__device__ __forceinline__ void build_wt(const float* __restrict__ W,
                                         float* __restrict__ Wt,
                                         int total, int idx, int stride) {
    for (int o = idx; o < total; o += stride) {
        int kt = o >> 11;
        int rem = o & 2047;
        int col = rem >> 4;
        int u = rem & 15;
        int t4 = u >> 2;
        int j = u & 3;
        int srck = kt * 16 + t4 + 4 * j;
        float v = W[srck * CC + col];
        Wt[o] = __uint_as_float(f2tf(v));
    }
}

__global__ void init_kernel(const float* __restrict__ Wa,
                            const float* __restrict__ Wp,
                            const float* __restrict__ kW) {
    int idx = blockIdx.x * blockDim.x + threadIdx.x;
    int stride = gridDim.x * blockDim.x;
    for (int i = idx; i < 2 * NP; i += stride) g_cnt[i] = 0;
    build_wt(Wa, g_Wat, FA * CC, idx, stride);
    build_wt(Wp, g_Wpt, FP * CC, idx, stride);
    build_wt(kW, g_kWt, CC * CC, idx, stride);
    if (idx < CC) {
        g_Sa[idx] = 0.f; g_Sb[idx] = 0.f;
        g_Saa[idx] = 0.f; g_Sbb[idx] = 0.f; g_Sab[idx] = 0.f;
    }
    if (idx < 2) g_wsum[idx] = 0.f;
}

// ---------------- alpha epilogue: logits from register accumulators ----------------
// acc[nt][0..1]=row r1 cols nt*8+t2..+1, acc[nt][2..3]=row r2.
// att flat layout == channel layout, so att value for acc[nt][j] is att[nt*8+t2+j].
__device__ __forceinline__ void alpha_epilogue(
        const float acc[16][4], const float* __restrict__ att,
        float* __restrict__ out, int r1, int r2, int Nrows, int t4) {
    int t2 = t4 * 2;
    float p1[8], p2[8];
#pragma unroll
    for (int h = 0; h < 8; h++) {
        int na = 2 * h, nb = 2 * h + 1;
        float2 aA = *(const float2*)(att + na * 8 + t2);
        float2 aB = *(const float2*)(att + nb * 8 + t2);
        p1[h] = acc[na][0] * aA.x + acc[na][1] * aA.y
              + acc[nb][0] * aB.x + acc[nb][1] * aB.y;
        p2[h] = acc[na][2] * aA.x + acc[na][3] * aA.y
              + acc[nb][2] * aB.x + acc[nb][3] * aB.y;
    }
#pragma unroll
    for (int h = 0; h < 8; h++) {
        p1[h] += __shfl_xor_sync(0xFFFFFFFFu, p1[h], 1);
        p1[h] += __shfl_xor_sync(0xFFFFFFFFu, p1[h], 2);
        p2[h] += __shfl_xor_sync(0xFFFFFFFFu, p2[h], 1);
        p2[h] += __shfl_xor_sync(0xFFFFFFFFu, p2[h], 2);
    }
#pragma unroll
    for (int h = 0; h < 8; h++) {
        if ((h & 3) == t4) {
            if (r1 < Nrows) out[r1 * 8 + h] = p1[h];
            if (r2 < Nrows) out[r2 * 8 + h] = p2[h];
        }
    }
}

// ---------------- gemm body (tf32 mma, permuted-B, alpha epilogue) ----------------
template <int KDIM, int NATT>
__device__ __forceinline__ void gemm_body(
        const float* __restrict__ X, const float* __restrict__ Wt,
        const float* __restrict__ bias, float* __restrict__ out,
        int Nrows, int bx, char* smraw,
        const float* __restrict__ att0, float* __restrict__ ao0,
        const float* __restrict__ att1, float* __restrict__ ao1,
        const float* __restrict__ att2, float* __restrict__ ao2) {
    float* As = (float*)smraw;
    float* Bs = (float*)(smraw + SM_A_BYTES);
    int tid = threadIdx.x, w = tid >> 5, lane = tid & 31;
    int row0 = bx * 128;

    int arow = tid >> 1, ak = (tid & 1) * 8;
    int garow = row0 + arow;
    int aok = (garow < Nrows) ? 16 : 0;
    const float* abase = X + (size_t)(aok ? garow : 0) * KDIM + ak;
    const float* bbase = Wt + tid * 8;

    uint32_t dA0 = (uint32_t)__cvta_generic_to_shared(&As[arow * APITCH + ak]);
    uint32_t dA1 = dA0 + SM_A_BYTES / 2;
    uint32_t dB0 = (uint32_t)__cvta_generic_to_shared(&Bs[tid * 8]);
    uint32_t dB1 = dB0 + SM_B_BYTES / 2;

    const int NT = KDIM / 16;
    cp16(dA0, abase, aok); cp16(dA0 + 16, abase + 4, aok);
    cp16(dB0, bbase, 16);  cp16(dB0 + 16, bbase + 4, 16);
    cp_commit();

    float acc[16][4];
#pragma unroll
    for (int nt = 0; nt < 16; nt++)
#pragma unroll
        for (int j = 0; j < 4; j++) acc[nt][j] = 0.f;

    int g = lane >> 2, t4 = lane & 3;

    for (int kt = 0; kt < NT; kt++) {
        if (kt + 1 < NT) {
            uint32_t dA = ((kt + 1) & 1) ? dA1 : dA0;
            uint32_t dB = ((kt + 1) & 1) ? dB1 : dB0;
            const float* ap = abase + (kt + 1) * 16;
            const float* bp = bbase + (size_t)(kt + 1) * 2048;
            cp16(dA, ap, aok); cp16(dA + 16, ap + 4, aok);
            cp16(dB, bp, 16);  cp16(dB + 16, bp + 4, 16);
            cp_commit();
            cp_wait1();
        } else {
            cp_wait0();
        }
        __syncthreads();

        const float* Ab = As + (kt & 1) * (128 * APITCH);
        const uint32_t* Bb = (const uint32_t*)(Bs + (kt & 1) * 2048);

        uint32_t afr[2][4];
#pragma unroll
        for (int s = 0; s < 2; s++) {
            int k = s * 8 + t4;
            afr[s][0] = f2tf(Ab[(w * 16 + g) * APITCH + k]);
            afr[s][1] = f2tf(Ab[(w * 16 + g + 8) * APITCH + k]);
            afr[s][2] = f2tf(Ab[(w * 16 + g) * APITCH + k + 4]);
            afr[s][3] = f2tf(Ab[(w * 16 + g + 8) * APITCH + k + 4]);
        }
#pragma unroll
        for (int nt = 0; nt < 16; nt++) {
            uint4 bq = *(const uint4*)&Bb[(nt * 8 + g) * 16 + t4 * 4];
            mma_tf32(acc[nt], afr[0], bq.x, bq.y);
            mma_tf32(acc[nt], afr[1], bq.z, bq.w);
        }
        __syncthreads();
    }

    int t2 = t4 * 2;
    int r1 = row0 + w * 16 + g;
    int r2 = r1 + 8;

    // add bias into accumulators (alpha must see biased h)
#pragma unroll
    for (int nt = 0; nt < 16; nt++) {
        float2 bb = *(const float2*)(bias + nt * 8 + t2);
        acc[nt][0] += bb.x; acc[nt][1] += bb.y;
        acc[nt][2] += bb.x; acc[nt][3] += bb.y;
    }
    // store h
#pragma unroll
    for (int nt = 0; nt < 16; nt++) {
        int col = nt * 8 + t2;
        if (r1 < Nrows)
            *(float2*)(out + (size_t)r1 * CC + col) = make_float2(acc[nt][0], acc[nt][1]);
        if (r2 < Nrows)
            *(float2*)(out + (size_t)r2 * CC + col) = make_float2(acc[nt][2], acc[nt][3]);
    }
    // attention logits from registers
    alpha_epilogue(acc, att0, ao0, r1, r2, Nrows, t4);
    if (NATT > 1) alpha_epilogue(acc, att1, ao1, r1, r2, Nrows, t4);
    if (NATT > 2) alpha_epilogue(acc, att2, ao2, r1, r2, Nrows, t4);
}

__device__ __forceinline__ void hist_body(const int* __restrict__ e_ap,
                                          const int* __restrict__ e_pp, int bx) {
    for (int idx = bx * 256 + threadIdx.x; idx < 2 * EE; idx += GH * 256) {
        int t = (idx >= EE);
        int e = idx - t * EE;
        const int* ed = t ? e_pp : e_ap;
        int dst = ed[EE + e];
        int r = atomicAdd(&g_cnt[t * NP + dst], 1);
        g_rank[idx] = r;
    }
}

// ---------------- phase1: gemm_a(+alpha) | gemm_p(+3 alphas) | hist ----------------
__global__ __launch_bounds__(256) void phase1_kernel(
        const float* __restrict__ xa, const float* __restrict__ ba,
        const float* __restrict__ xp, const float* __restrict__ bp,
        const float* __restrict__ att_src_ap, const float* __restrict__ att_dst_ap,
        const float* __restrict__ att_src_pp, const float* __restrict__ att_dst_pp,
        const int* __restrict__ e_ap, const int* __restrict__ e_pp) {
    __shared__ __align__(16) char sm[SM_GEMM_BYTES];
    int bx = blockIdx.x;
    if (bx < GA) {
        gemm_body<FA, 1>(xa, g_Wat, ba, g_h_a, NA, bx, sm,
                         att_src_ap, g_as_ap, 0, 0, 0, 0);
    } else if (bx < GA + GP) {
        gemm_body<FP, 3>(xp, g_Wpt, bp, g_h_p, NP, bx - GA, sm,
                         att_dst_ap, g_ad_ap, att_src_pp, g_as_pp,
                         att_dst_pp, g_ad_pp);
    } else {
        hist_body(e_ap, e_pp, bx - GA - GP);
    }
}

// ---------------- scan (shfl-based) ----------------
#define SCAN_T 1024
#define SCAN_CHUNK 49
__global__ void scan_kernel() {
    int t = blockIdx.x;
    int tid = threadIdx.x;
    int lane = tid & 31, wid = tid >> 5;
    const int* cnt = g_cnt + t * NP;
    int* rowptr = g_rowptr + t * (NP + 1);

    int lo = tid * SCAN_CHUNK;
    int hi = lo + SCAN_CHUNK; if (hi > NP) hi = NP;
    int tsum = 0;
    for (int i = lo; i < hi; i++) tsum += cnt[i];

    int incl = tsum;
#pragma unroll
    for (int o = 1; o < 32; o <<= 1) {
        int v = __shfl_up_sync(0xFFFFFFFFu, incl, o);
        if (lane >= o) incl += v;
    }
    __shared__ int wtot[32];
    if (lane == 31) wtot[wid] = incl;
    __syncthreads();
    if (wid == 0) {
        int v = wtot[lane];
#pragma unroll
        for (int o = 1; o < 32; o <<= 1) {
            int u = __shfl_up_sync(0xFFFFFFFFu, v, o);
            if (lane >= o) v += u;
        }
        wtot[lane] = v;
    }
    __syncthreads();
    int running = (wid ? wtot[wid - 1] : 0) + incl - tsum;
    for (int i = lo; i < hi; i++) {
        rowptr[i] = running;
        running += cnt[i];
    }
    if (tid == 0) rowptr[NP] = EE;
}

// ---------------- scatter (atomic-free, rank-based) ----------------
__global__ void scatter_kernel(const int* __restrict__ e_ap,
                               const int* __restrict__ e_pp) {
    int idx = blockIdx.x * blockDim.x + threadIdx.x;
    if (idx >= 2 * EE) return;
    int t = (idx >= EE);
    int e = idx - t * EE;
    const int* ed = t ? e_pp : e_ap;
    int src = ed[e];
    int dst = ed[EE + e];
    int pos = g_rowptr[t * (NP + 1) + dst] + g_rank[idx];
    g_srcs[(size_t)t * EE + pos] = src;
}

// ---------------- merged edge kernel (both types; warp per dst) ----------------
__global__ __launch_bounds__(256) void edge_kernel() {
    __shared__ int   sh_s[8][32];
    __shared__ float sh_e[8][32][8];
    int warp = threadIdx.x >> 5;
    int lane = threadIdx.x & 31;
    int gw = blockIdx.x * 8 + warp;
    if (gw >= 2 * NP) return;
    int t = (gw >= NP);
    int dst = gw - t * NP;

    const int* rowptr = g_rowptr + t * (NP + 1);
    const int* srcs = g_srcs + (size_t)t * EE;
    const float* as = t ? g_as_pp : g_as_ap;
    const float* ad = t ? g_ad_pp : g_ad_ap;
    const float* Hsrc = t ? g_h_p : g_h_a;
    float* outp = g_out01 + (size_t)t * NP * CC;

    int base = rowptr[dst];
    int deg = rowptr[dst + 1] - base;

    float* ow = outp + (size_t)dst * CC;
    if (deg == 0) {
        *(float4*)(ow + lane * 4) = make_float4(0.f, 0.f, 0.f, 0.f);
        return;
    }

    float4 ad0 = *(const float4*)(ad + dst * HH);
    float4 ad1 = *(const float4*)(ad + dst * HH + 4);
    float advs[8] = {ad0.x, ad0.y, ad0.z, ad0.w, ad1.x, ad1.y, ad1.z, ad1.w};

    int myh = lane >> 2;
    float4 acc = make_float4(0.f, 0.f, 0.f, 0.f);
    float denom = 0.f;

    for (int chunk = 0; chunk < deg; chunk += 32) {
        int n = min(32, deg - chunk);
        if (lane < n) {
            int s = srcs[base + chunk + lane];
            sh_s[warp][lane] = s;
            float4 a0 = *(const float4*)(as + s * HH);
            float4 a1 = *(const float4*)(as + s * HH + 4);
            float al[8] = {a0.x, a0.y, a0.z, a0.w, a1.x, a1.y, a1.z, a1.w};
            float e[8];
#pragma unroll
            for (int h = 0; h < 8; h++) {
                float v = al[h] + advs[h];
                v = (v >= 0.f) ? v : 0.2f * v;
                e[h] = __expf(v);
            }
            *(float4*)&sh_e[warp][lane][0] = make_float4(e[0], e[1], e[2], e[3]);
            *(float4*)&sh_e[warp][lane][4] = make_float4(e[4], e[5], e[6], e[7]);
        }
        __syncwarp();
#pragma unroll 4
        for (int i = 0; i < n; i++) {
            int s = sh_s[warp][i];
            float wgt = sh_e[warp][i][myh];
            float4 hv = *(const float4*)(Hsrc + (size_t)s * CC + lane * 4);
            denom += wgt;
            acc.x += wgt * hv.x; acc.y += wgt * hv.y;
            acc.z += wgt * hv.z; acc.w += wgt * hv.w;
        }
        __syncwarp();
    }
    float inv = 1.f / denom;
    float4 v = make_float4(fmaxf(acc.x * inv, 0.f), fmaxf(acc.y * inv, 0.f),
                           fmaxf(acc.z * inv, 0.f), fmaxf(acc.w * inv, 0.f));
    *(float4*)(ow + lane * 4) = v;
}

// ---------------- phase5 bodies ----------------
__device__ __forceinline__ void semantic_body(
        const float* __restrict__ kb, const float* __restrict__ q,
        int rsel, int bx, char* smraw) {
    const float* X = g_out01 + (size_t)rsel * NP * CC;
    const float* Wt = g_kWt;
    float* As = (float*)smraw;
    float* Bs = (float*)(smraw + SM_A_BYTES);
    float* red = (float*)(smraw + SM_GEMM_BYTES);
    int tid = threadIdx.x, w = tid >> 5, lane = tid & 31;
    int row0 = bx * 128;

    int arow = tid >> 1, ak = (tid & 1) * 8;
    int garow = row0 + arow;
    int aok = (garow < NP) ? 16 : 0;
    const float* abase = X + (size_t)(aok ? garow : 0) * CC + ak;
    const float* bbase = Wt + tid * 8;

    uint32_t dA0 = (uint32_t)__cvta_generic_to_shared(&As[arow * APITCH + ak]);
    uint32_t dA1 = dA0 + SM_A_BYTES / 2;
    uint32_t dB0 = (uint32_t)__cvta_generic_to_shared(&Bs[tid * 8]);
    uint32_t dB1 = dB0 + SM_B_BYTES / 2;

    const int NT = CC / 16;
    cp16(dA0, abase, aok); cp16(dA0 + 16, abase + 4, aok);
    cp16(dB0, bbase, 16);  cp16(dB0 + 16, bbase + 4, 16);
    cp_commit();

    float acc[16][4];
#pragma unroll
    for (int nt = 0; nt < 16; nt++)
#pragma unroll
        for (int j = 0; j < 4; j++) acc[nt][j] = 0.f;

    int g = lane >> 2, t4 = lane & 3;

    for (int kt = 0; kt < NT; kt++) {
        if (kt + 1 < NT) {
            uint32_t dA = ((kt + 1) & 1) ? dA1 : dA0;
            uint32_t dB = ((kt + 1) & 1) ? dB1 : dB0;
            const float* ap = abase + (kt + 1) * 16;
            const float* bp = bbase + (size_t)(kt + 1) * 2048;
            cp16(dA, ap, aok); cp16(dA + 16, ap + 4, aok);
            cp16(dB, bp, 16);  cp16(dB + 16, bp + 4, 16);
            cp_commit();
            cp_wait1();
        } else {
            cp_wait0();
        }
        __syncthreads();

        const float* Ab = As + (kt & 1) * (128 * APITCH);
        const uint32_t* Bb = (const uint32_t*)(Bs + (kt & 1) * 2048);

        uint32_t afr[2][4];
#pragma unroll
        for (int s = 0; s < 2; s++) {
            int k = s * 8 + t4;
            afr[s][0] = f2tf(Ab[(w * 16 + g) * APITCH + k]);
            afr[s][1] = f2tf(Ab[(w * 16 + g + 8) * APITCH + k]);
            afr[s][2] = f2tf(Ab[(w * 16 + g) * APITCH + k + 4]);
            afr[s][3] = f2tf(Ab[(w * 16 + g + 8) * APITCH + k + 4]);
        }
#pragma unroll
        for (int nt = 0; nt < 16; nt++) {
            uint4 bq = *(const uint4*)&Bb[(nt * 8 + g) * 16 + t4 * 4];
            mma_tf32(acc[nt], afr[0], bq.x, bq.y);
            mma_tf32(acc[nt], afr[1], bq.z, bq.w);
        }
        __syncthreads();
    }

    int t2 = t4 * 2;
    int r1 = row0 + w * 16 + g;
    int r2 = r1 + 8;
    float part = 0.f;
#pragma unroll
    for (int nt = 0; nt < 16; nt++) {
        int col = nt * 8 + t2;
        float2 kb2 = *(const float2*)(kb + col);
        float2 q2 = *(const float2*)(q + col);
        if (r1 < NP)
            part += tanh_fast(acc[nt][0] + kb2.x) * q2.x
                  + tanh_fast(acc[nt][1] + kb2.y) * q2.y;
        if (r2 < NP)
            part += tanh_fast(acc[nt][2] + kb2.x) * q2.x
                  + tanh_fast(acc[nt][3] + kb2.y) * q2.y;
    }
#pragma unroll
    for (int o = 16; o; o >>= 1) part += __shfl_xor_sync(0xFFFFFFFFu, part, o);
    if (lane == 0) red[w] = part;
    __syncthreads();
    if (tid == 0) {
        float s = 0.f;
#pragma unroll
        for (int i = 0; i < 8; i++) s += red[i];
        atomicAdd(&g_wsum[rsel], s);
    }
}

#define STAT_ROWS 512
__device__ __forceinline__ void stats5_body(int bx) {
    int tid = threadIdx.x;
    int c = tid & 127;
    int half = tid >> 7;
    const float* o0 = g_out01;
    const float* o1 = g_out01 + (size_t)NP * CC;
    int r0 = bx * STAT_ROWS + half;
    int r1 = bx * STAT_ROWS + STAT_ROWS; if (r1 > NP) r1 = NP;
    float sa = 0.f, sb = 0.f, saa = 0.f, sbb = 0.f, sab = 0.f;
    for (int r = r0; r < r1; r += 2) {
        float a = o0[(size_t)r * CC + c];
        float b = o1[(size_t)r * CC + c];
        sa += a; sb += b;
        saa += a * a; sbb += b * b; sab += a * b;
    }
    atomicAdd(&g_Sa[c], sa);
    atomicAdd(&g_Sb[c], sb);
    atomicAdd(&g_Saa[c], saa);
    atomicAdd(&g_Sbb[c], sbb);
    atomicAdd(&g_Sab[c], sab);
}

// ---------------- phase5: semantic (r=0 | r=1) | stats ----------------
__global__ __launch_bounds__(256) void phase5_kernel(
        const float* __restrict__ kb, const float* __restrict__ q) {
    __shared__ __align__(16) char sm[SM_GEMM_BYTES + 32];
    int bx = blockIdx.x;
    if (bx < GSEM) {
        int rsel = (bx >= GSEM / 2);
        semantic_body(kb, q, rsel, bx - rsel * (GSEM / 2), sm);
    } else {
        stats5_body(bx - GSEM);
    }
}

// ---------------- final: inline beta + norm params, normalize + classify ----------------
__global__ __launch_bounds__(256) void final_kernel(
        const float* __restrict__ norm_w, const float* __restrict__ norm_b,
        const float* __restrict__ norm_ms,
        const float* __restrict__ linW, const float* __restrict__ linb,
        float* __restrict__ y) {
    __shared__ float rowbuf[16][CC];
    __shared__ float lw[CC * OUTC];
    __shared__ float lb[OUTC];
    __shared__ float snA[CC], snB[CC];
    int tid = threadIdx.x;

    // beta (cheap, redundant per thread)
    float w0 = g_wsum[0] * (1.f / NP);
    float w1 = g_wsum[1] * (1.f / NP);
    float m = fmaxf(w0, w1);
    float e0 = expf(w0 - m), e1 = expf(w1 - m);
    float ssum = e0 + e1;
    float b0 = e0 / ssum, b1 = e1 / ssum;

    for (int i = tid; i < CC * OUTC; i += 256) lw[i] = linW[i];
    if (tid < OUTC) lb[tid] = linb[tid];
    if (tid < CC) {
        int c = tid;
        float mean = (b0 * g_Sa[c] + b1 * g_Sb[c]) * (1.f / NP);
        float eo2 = (b0 * b0 * g_Saa[c] + 2.f * b0 * b1 * g_Sab[c]
                     + b1 * b1 * g_Sbb[c]) * (1.f / NP);
        float mm = mean * norm_ms[c];
        float var = eo2 - 2.f * mm * mean + mm * mm;
        float A = norm_w[c] * rsqrtf(var + EPSV);
        snA[c] = A;
        snB[c] = norm_b[c] - mm * A;
    }
    __syncthreads();

    const float* o0 = g_out01;
    const float* o1 = g_out01 + (size_t)NP * CC;
    int nrow0 = blockIdx.x * 16;
#pragma unroll
    for (int j = 0; j < 8; j++) {
        int i = tid + j * 256;
        int r = i >> 7, c = i & 127;
        int gr = nrow0 + r;
        float v = 0.f;
        if (gr < NP) {
            v = b0 * o0[(size_t)gr * CC + c] + b1 * o1[(size_t)gr * CC + c];
            v = v * snA[c] + snB[c];
        }
        rowbuf[r][c] = v;
    }
    __syncthreads();
    int r = tid >> 4, o = tid & 15;
    int gr = nrow0 + r;
    if (gr < NP) {
        float s = lb[o];
#pragma unroll
        for (int c = 0; c < CC; c++) s += rowbuf[r][c] * lw[c * OUTC + o];
        y[(size_t)gr * OUTC + o] = s;
    }
}

// ---------------- launch ----------------
extern "C" void kernel_launch(void* const* d_in, const int* in_sizes, int n_in,
                              void* d_out, int out_size) {
    const float* x_author = (const float*)d_in[0];
    const float* x_paper  = (const float*)d_in[1];
    const float* W_a      = (const float*)d_in[2];
    const float* b_a      = (const float*)d_in[3];
    const float* W_p      = (const float*)d_in[4];
    const float* b_p      = (const float*)d_in[5];
    const float* att_src_ap = (const float*)d_in[6];
    const float* att_dst_ap = (const float*)d_in[7];
    const float* att_src_pp = (const float*)d_in[8];
    const float* att_dst_pp = (const float*)d_in[9];
    const float* k_W      = (const float*)d_in[10];
    const float* k_b      = (const float*)d_in[11];
    const float* q        = (const float*)d_in[12];
    const float* norm_w   = (const float*)d_in[13];
    const float* norm_b   = (const float*)d_in[14];
    const float* norm_ms  = (const float*)d_in[15];
    const float* lin_W    = (const float*)d_in[16];
    const float* lin_b    = (const float*)d_in[17];
    const int*   edge_ap  = (const int*)d_in[18];
    const int*   edge_pp  = (const int*)d_in[19];
    float* y = (float*)d_out;

    // 0. init
    init_kernel<<<256, 256>>>(W_a, W_p, k_W);

    // 1. gemm_a(+alpha) | gemm_p(+3 alphas) | hist(+rank)
    phase1_kernel<<<GA + GP + GH, 256>>>(x_author, b_a, x_paper, b_p,
                                         att_src_ap, att_dst_ap,
                                         att_src_pp, att_dst_pp,
                                         edge_ap, edge_pp);

    // 2. prefix scan
    scan_kernel<<<2, SCAN_T>>>();

    // 3. scatter (atomic-free)
    scatter_kernel<<<(2 * EE + 255) / 256, 256>>>(edge_ap, edge_pp);

    // 4. fused edge softmax + aggregation, both types
    edge_kernel<<<(2 * NP + 7) / 8, 256>>>();

    // 5. semantic gemms | beta-independent stats
    phase5_kernel<<<GSEM + GST, 256>>>(k_b, q);

    // 6. normalize + classify (beta + norm params inlined)
    final_kernel<<<(NP + 15) / 16, 256>>>(norm_w, norm_b, norm_ms,
                                          lin_W, lin_b, y);
}